// round 9
// baseline (speedup 1.0000x reference)
#include <cuda_runtime.h>
#include <cuda_fp16.h>
#include <cstdint>

#define B_DIM 8
#define L_DIM 4096
#define D_DIM 1024
#define N_DIM 128
#define M_TOTAL (B_DIM * L_DIM)   // 32768
#define CHUNK 64
#define NCHUNK (L_DIM / CHUNK)    // 64
#define TOT_CHUNKS (B_DIM * NCHUNK) // 512

#define BW_SCALE 256.0f
#define BW_DESCALE (1.0f / 256.0f)

// Scratch (no cudaMalloc allowed)
__device__ float g_xproj[(size_t)M_TOTAL * N_DIM];
__device__ float g_carry[TOT_CHUNKS * N_DIM];
__device__ float g_prefix[TOT_CHUNKS * N_DIM];
__device__ __half g_hsh[(size_t)M_TOTAL * N_DIM];
__device__ __half g_Bwh[N_DIM * D_DIM];
__device__ __half g_Bwl[N_DIM * D_DIM];
__device__ __half g_Cwh[D_DIM * N_DIM];
__device__ __half g_Cwl[D_DIM * N_DIM];

typedef unsigned long long u64;
typedef uint32_t u32;

__device__ __forceinline__ u32 smem_to_u32(const void* p) {
    u32 a;
    asm("{ .reg .u64 t; cvta.to.shared.u64 t, %1; cvt.u32.u64 %0, t; }"
        : "=r"(a) : "l"(p));
    return a;
}
__device__ __forceinline__ u32 swz(u32 o) { return o ^ ((o >> 3) & 0x70); }

__device__ __forceinline__ void ldsm4(u32* r, u32 addr) {
    asm volatile("ldmatrix.sync.aligned.m8n8.x4.shared.b16 {%0,%1,%2,%3}, [%4];"
                 : "=r"(r[0]), "=r"(r[1]), "=r"(r[2]), "=r"(r[3]) : "r"(addr));
}
__device__ __forceinline__ void mma16816(float* c, const u32* a, const u32* b) {
    asm volatile("mma.sync.aligned.m16n8k16.row.col.f32.f16.f16.f32 "
                 "{%0,%1,%2,%3}, {%4,%5,%6,%7}, {%8,%9}, {%0,%1,%2,%3};"
                 : "+f"(c[0]), "+f"(c[1]), "+f"(c[2]), "+f"(c[3])
                 : "r"(a[0]), "r"(a[1]), "r"(a[2]), "r"(a[3]),
                   "r"(b[0]), "r"(b[1]));
}
__device__ __forceinline__ u64 pack_f16x4(float a, float b, float c, float d) {
    __half2 p0 = __floats2half2_rn(a, b);
    __half2 p1 = __floats2half2_rn(c, d);
    u32 lo = *(u32*)&p0, hi = *(u32*)&p1;
    return ((u64)hi << 32) | lo;
}
#define CP_ASYNC16(dst, src) \
    asm volatile("cp.async.cg.shared.global [%0], [%1], 16;" :: "r"(dst), "l"(src))
#define CP_COMMIT() asm volatile("cp.async.commit_group;")
#define CP_WAIT0() asm volatile("cp.async.wait_group 0;")
#define CP_WAIT1() asm volatile("cp.async.wait_group 1;")

// ───────── GEMM1: xproj = x @ B_w^T  (x single fp16, B_w = scaled 2-term fp16) ─────
// CTA 128x128, warp tile 64x32, KC=32 fp32, 2 stages, chains Ah*Bh + Ah*Bl.
// Stage: A @0 (128 rows x 128B, fp16 in first 64B), B @16384 (128 x [Bh 64B|Bl 64B]).
__global__ void __launch_bounds__(256, 2)
gemm1_hmma(const float* __restrict__ A,
           const __half* __restrict__ Bwh, const __half* __restrict__ Bwl,
           float* __restrict__ C)
{
    constexpr int KTOT = D_DIM;
    constexpr int KC = 32;
    constexpr int NC = KTOT / KC;      // 32
    constexpr int STAGE = 32768;

    extern __shared__ char dsm[];
    const u32 raw = smem_to_u32(dsm);
    const u32 base = (raw + 1023u) & ~1023u;
    char* dbase = dsm + (base - raw);

    const int tid  = threadIdx.x;
    const int lane = tid & 31;
    const int warp = tid >> 5;
    const int wr = warp & 1;
    const int wc = warp >> 1;
    const long row0 = (long)blockIdx.y * 128;

    const int r  = tid >> 1;
    const int hv = tid & 1;
    const int cf0 = hv * 16;
    const float* Arow = A + (row0 + r) * (long)KTOT;
    const __half* Bsrc = (hv ? Bwl : Bwh) + (size_t)r * KTOT;

    const int g  = lane >> 3;
    const int ln = lane & 7;
    const int rA = wr * 64 + (g & 1) * 8 + ln;
    const int cA = (g >> 1) * 16;
    const int rB = wc * 32 + (g >> 1) * 8 + ln;
    const int cB = (g & 1) * 16;

    float acc[4][4][4];
#pragma unroll
    for (int i = 0; i < 4; i++)
#pragma unroll
        for (int j = 0; j < 4; j++)
#pragma unroll
            for (int q = 0; q < 4; q++) acc[i][j][q] = 0.0f;

    // prologue: prefetch A fp32 chunk0; issue B chunk0
    float4 pa[4];
#pragma unroll
    for (int q = 0; q < 4; q++) pa[q] = *(const float4*)(Arow + cf0 + q * 4);
    {
        const u32 bdst = base + 16384;
#pragma unroll
        for (int i = 0; i < 4; i++)
            CP_ASYNC16(bdst + swz((u32)r * 128 + hv * 64 + i * 16), Bsrc + i * 8);
        CP_COMMIT();
    }

    for (int c = 0; c < NC; c++) {
        const int s = c & 1;
        char* bufA = dbase + s * STAGE;

        // convert A chunk c (single fp16, no residual)
#pragma unroll
        for (int q = 0; q < 4; q++) {
            float4 v = pa[q];
            const u32 cbyte = (u32)(cf0 + q * 4) * 2;
            *(u64*)(bufA + swz((u32)r * 128 + cbyte)) =
                pack_f16x4(v.x, v.y, v.z, v.w);
        }
        // issue B chunk c+1 into other stage
        if (c + 1 < NC) {
            const u32 bdst = base + ((c + 1) & 1) * STAGE + 16384;
            const __half* src = Bsrc + (c + 1) * KC;
#pragma unroll
            for (int i = 0; i < 4; i++)
                CP_ASYNC16(bdst + swz((u32)r * 128 + hv * 64 + i * 16), src + i * 8);
            CP_COMMIT();
            CP_WAIT1();
        } else {
            CP_WAIT0();
        }
        __syncthreads();

        // prefetch A fp32 chunk c+1 (overlaps MMA)
        if (c + 1 < NC) {
            const int kn = (c + 1) * KC;
#pragma unroll
            for (int q = 0; q < 4; q++)
                pa[q] = *(const float4*)(Arow + kn + cf0 + q * 4);
        }

        const u32 ab = base + s * STAGE;
        const u32 bb = ab + 16384;
#pragma unroll
        for (int ks = 0; ks < 2; ks++) {
            const u32 kA = (u32)(ks * 32 + cA);
            const u32 kB = (u32)(ks * 32 + cB);
            u32 ah[4][4], bf[2][4];
#pragma unroll
            for (int mt = 0; mt < 4; mt++)
                ldsm4(ah[mt], ab + swz((u32)(rA + mt * 16) * 128 + kA));
            // Bh chain
#pragma unroll
            for (int p = 0; p < 2; p++)
                ldsm4(bf[p], bb + swz((u32)(rB + p * 16) * 128 + kB));
#pragma unroll
            for (int mt = 0; mt < 4; mt++)
#pragma unroll
                for (int nt = 0; nt < 4; nt++)
                    mma16816(acc[mt][nt], ah[mt], &bf[nt >> 1][(nt & 1) * 2]);
            // Bl chain
#pragma unroll
            for (int p = 0; p < 2; p++)
                ldsm4(bf[p], bb + swz((u32)(rB + p * 16) * 128 + 64 + kB));
#pragma unroll
            for (int mt = 0; mt < 4; mt++)
#pragma unroll
                for (int nt = 0; nt < 4; nt++)
                    mma16816(acc[mt][nt], ah[mt], &bf[nt >> 1][(nt & 1) * 2]);
        }
        __syncthreads();
    }

    // epilogue with exact power-of-2 descale
    const int er = lane >> 2;
    const int ec = (lane & 3) * 2;
#pragma unroll
    for (int mt = 0; mt < 4; mt++)
#pragma unroll
        for (int nt = 0; nt < 4; nt++) {
            const long m = row0 + wr * 64 + mt * 16 + er;
            const long n = wc * 32 + nt * 8 + ec;
            *(float2*)(C + m * (long)N_DIM + n) =
                make_float2(acc[mt][nt][0] * BW_DESCALE, acc[mt][nt][1] * BW_DESCALE);
            *(float2*)(C + (m + 8) * (long)N_DIM + n) =
                make_float2(acc[mt][nt][2] * BW_DESCALE, acc[mt][nt][3] * BW_DESCALE);
        }
}

// ───────── GEMM2: y = hs @ C_w^T + x*Dp  (hs single fp16, C_w 2-term fp16) ─────
// K'=64 per chunk, 2 chunks, double buffer. Stage 48KB: A@0 16KB, Ch@16384, Cl@32768.
__global__ void __launch_bounds__(256, 2)
gemm2_hmma(const __half* __restrict__ hsh,
           const __half* __restrict__ Cwh, const __half* __restrict__ Cwl,
           float* __restrict__ C,
           const float* __restrict__ X, const float* __restrict__ Dp)
{
    constexpr int NVC = 2;
    constexpr int STAGE = 49152;

    extern __shared__ char dsm[];
    const u32 raw = smem_to_u32(dsm);
    const u32 base = (raw + 1023u) & ~1023u;

    const int tid  = threadIdx.x;
    const int lane = tid & 31;
    const int warp = tid >> 5;
    const int wr = warp & 1;
    const int wc = warp >> 1;
    const long row0 = (long)blockIdx.y * 128;
    const long col0 = (long)blockIdx.x * 128;

    const int r2 = tid >> 1;
    const int hv = tid & 1;

    const int g  = lane >> 3;
    const int ln = lane & 7;
    const int rA = wr * 64 + (g & 1) * 8 + ln;
    const int cA = (g >> 1) * 16;
    const int rB = wc * 32 + (g >> 1) * 8 + ln;
    const int cB = (g & 1) * 16;

    float acc[4][4][4];
#pragma unroll
    for (int i = 0; i < 4; i++)
#pragma unroll
        for (int j = 0; j < 4; j++)
#pragma unroll
            for (int q = 0; q < 4; q++) acc[i][j][q] = 0.0f;

    auto issue = [&](int vc) {
        const u32 sb = base + (vc & 1) * STAGE;
        const int kk = vc * 64;
        const __half* asrc = hsh + (row0 + r2) * (long)N_DIM + kk + hv * 32;
        const __half* bh   = Cwh + (col0 + r2) * (long)N_DIM + kk + hv * 32;
        const __half* bl   = Cwl + (col0 + r2) * (long)N_DIM + kk + hv * 32;
#pragma unroll
        for (int i = 0; i < 4; i++)
            CP_ASYNC16(sb + swz((u32)r2 * 128 + hv * 64 + i * 16), asrc + i * 8);
#pragma unroll
        for (int i = 0; i < 4; i++)
            CP_ASYNC16(sb + 16384 + swz((u32)r2 * 128 + hv * 64 + i * 16), bh + i * 8);
#pragma unroll
        for (int i = 0; i < 4; i++)
            CP_ASYNC16(sb + 32768 + swz((u32)r2 * 128 + hv * 64 + i * 16), bl + i * 8);
        CP_COMMIT();
    };

    issue(0);
    issue(1);

    for (int vc = 0; vc < NVC; vc++) {
        if (vc + 1 < NVC) { CP_WAIT1(); } else { CP_WAIT0(); }
        __syncthreads();

        const u32 ab  = base + (vc & 1) * STAGE;
        const u32 bbh = ab + 16384;
        const u32 bbl = ab + 32768;
#pragma unroll
        for (int ks = 0; ks < 4; ks++) {
            const u32 kA = (u32)(ks * 32 + cA);
            const u32 kB = (u32)(ks * 32 + cB);
            u32 ah[4][4], bf[2][4];
#pragma unroll
            for (int mt = 0; mt < 4; mt++)
                ldsm4(ah[mt], ab + swz((u32)(rA + mt * 16) * 128 + kA));
            // Ch chain
#pragma unroll
            for (int p = 0; p < 2; p++)
                ldsm4(bf[p], bbh + swz((u32)(rB + p * 16) * 128 + kB));
#pragma unroll
            for (int mt = 0; mt < 4; mt++)
#pragma unroll
                for (int nt = 0; nt < 4; nt++)
                    mma16816(acc[mt][nt], ah[mt], &bf[nt >> 1][(nt & 1) * 2]);
            // Cl chain
#pragma unroll
            for (int p = 0; p < 2; p++)
                ldsm4(bf[p], bbl + swz((u32)(rB + p * 16) * 128 + kB));
#pragma unroll
            for (int mt = 0; mt < 4; mt++)
#pragma unroll
                for (int nt = 0; nt < 4; nt++)
                    mma16816(acc[mt][nt], ah[mt], &bf[nt >> 1][(nt & 1) * 2]);
        }
    }

    const int er = lane >> 2;
    const int ec = (lane & 3) * 2;
#pragma unroll
    for (int mt = 0; mt < 4; mt++)
#pragma unroll
        for (int nt = 0; nt < 4; nt++) {
            const long m = row0 + wr * 64 + mt * 16 + er;
            const long n = col0 + wc * 32 + nt * 8 + ec;
            float2 dv = *(const float2*)(Dp + n);
            float2 x0 = *(const float2*)(X + m * (long)D_DIM + n);
            float2 x1 = *(const float2*)(X + (m + 8) * (long)D_DIM + n);
            float2 o0, o1;
            o0.x = fmaf(x0.x, dv.x, acc[mt][nt][0]);
            o0.y = fmaf(x0.y, dv.y, acc[mt][nt][1]);
            o1.x = fmaf(x1.x, dv.x, acc[mt][nt][2]);
            o1.y = fmaf(x1.y, dv.y, acc[mt][nt][3]);
            *(float2*)(C + m * (long)D_DIM + n) = o0;
            *(float2*)(C + (m + 8) * (long)D_DIM + n) = o1;
        }
}

// ───────── weight presplit (fp16 2-term, optional scale) ─────────
__global__ void split2h_kernel(const float* __restrict__ src,
                               __half* __restrict__ dh, __half* __restrict__ dl,
                               int n, float scale)
{
    int i = blockIdx.x * blockDim.x + threadIdx.x;
    if (i < n) {
        float v = src[i] * scale;
        __half h = __float2half_rn(v);
        dh[i] = h;
        dl[i] = __float2half_rn(v - __half2float(h));
    }
}

// ───────── scan: 3 passes, CHUNK=64 ─────────
__global__ void __launch_bounds__(128)
scan_carry(const float* __restrict__ xproj, float* __restrict__ carry,
           const float* __restrict__ log_A)
{
    int n = threadIdx.x;
    int chunk = blockIdx.x;
    int b = blockIdx.y;
    float A = expf(log_A[n]);
    const float* src = xproj + ((size_t)b * L_DIM + (size_t)chunk * CHUNK) * N_DIM + n;
    float h = 0.0f;
#pragma unroll 8
    for (int i = 0; i < CHUNK; i++)
        h = fmaf(A, h, src[(size_t)i * N_DIM]);
    carry[(b * NCHUNK + chunk) * N_DIM + n] = h;
}

__global__ void __launch_bounds__(128)
carry_scan(const float* __restrict__ carry, float* __restrict__ prefix,
           const float* __restrict__ log_A)
{
    int n = threadIdx.x;
    int b = blockIdx.x;
    float Ac = expf((float)CHUNK * log_A[n]);
    float h = 0.0f;
#pragma unroll
    for (int c = 0; c < NCHUNK; c++) {
        prefix[(b * NCHUNK + c) * N_DIM + n] = h;   // exclusive
        h = fmaf(Ac, h, carry[(b * NCHUNK + c) * N_DIM + n]);
    }
}

__global__ void __launch_bounds__(128)
scan_split(const float* __restrict__ xproj, const float* __restrict__ prefix,
           __half* __restrict__ hsh, const float* __restrict__ log_A)
{
    int n = threadIdx.x;
    int chunk = blockIdx.x;
    int b = blockIdx.y;
    float A = expf(log_A[n]);
    size_t bo = ((size_t)b * L_DIM + (size_t)chunk * CHUNK) * N_DIM + n;
    const float* src = xproj + bo;
    float h = prefix[(b * NCHUNK + chunk) * N_DIM + n];
#pragma unroll 8
    for (int i = 0; i < CHUNK; i++) {
        h = fmaf(A, h, src[(size_t)i * N_DIM]);
        hsh[bo + (size_t)i * N_DIM] = __float2half_rn(h);
    }
}

__global__ void final_state_kernel(const float* __restrict__ xproj,
                                   float* __restrict__ fs)
{
    int n = threadIdx.x;
    float s = 0.0f;
#pragma unroll
    for (int b = 0; b < B_DIM; b++)
        s += xproj[((size_t)b * L_DIM + (L_DIM - 1)) * N_DIM + n];
    s *= (1.0f / B_DIM);
#pragma unroll
    for (int b = 0; b < B_DIM; b++)
        fs[b * N_DIM + n] = s;
}

// ─────────────────────────────── launch ───────────────────────────────
extern "C" void kernel_launch(void* const* d_in, const int* in_sizes, int n_in,
                              void* d_out, int out_size)
{
    const float* x       = (const float*)d_in[0];
    const float* B_w     = (const float*)d_in[1];
    const float* C_w     = (const float*)d_in[2];
    const float* log_A   = (const float*)d_in[3];
    const float* D_param = (const float*)d_in[4];

    float* y  = (float*)d_out;
    float* fs = y + ((size_t)out_size - (size_t)B_DIM * N_DIM);

    float *xproj, *carry, *prefix;
    __half *hsh, *Bwh, *Bwl, *Cwh, *Cwl;
    cudaGetSymbolAddress((void**)&xproj, g_xproj);
    cudaGetSymbolAddress((void**)&carry, g_carry);
    cudaGetSymbolAddress((void**)&prefix, g_prefix);
    cudaGetSymbolAddress((void**)&hsh, g_hsh);
    cudaGetSymbolAddress((void**)&Bwh, g_Bwh);
    cudaGetSymbolAddress((void**)&Bwl, g_Bwl);
    cudaGetSymbolAddress((void**)&Cwh, g_Cwh);
    cudaGetSymbolAddress((void**)&Cwl, g_Cwl);

    const int SMEM1 = 2 * 32768 + 1024;   // 66560
    const int SMEM2 = 2 * 49152 + 1024;   // 99328
    cudaFuncSetAttribute(gemm1_hmma, cudaFuncAttributeMaxDynamicSharedMemorySize, SMEM1);
    cudaFuncSetAttribute(gemm2_hmma, cudaFuncAttributeMaxDynamicSharedMemorySize, SMEM2);

    // presplit weights (B_w scaled x256 so the low term stays fp16-normal)
    split2h_kernel<<<(N_DIM * D_DIM + 255) / 256, 256>>>(B_w, Bwh, Bwl, N_DIM * D_DIM, BW_SCALE);
    split2h_kernel<<<(D_DIM * N_DIM + 255) / 256, 256>>>(C_w, Cwh, Cwl, D_DIM * N_DIM, 1.0f);

    // GEMM1: xproj = x @ B_w^T  (descaled in epilogue)
    {
        dim3 grid(1, M_TOTAL / 128);
        gemm1_hmma<<<grid, 256, SMEM1>>>(x, Bwh, Bwl, xproj);
    }

    // scan: carries -> prefix -> fused global scan + fp16 store
    {
        dim3 grid(NCHUNK, B_DIM);
        scan_carry<<<grid, 128>>>(xproj, carry, log_A);
        carry_scan<<<B_DIM, 128>>>(carry, prefix, log_A);
        scan_split<<<grid, 128>>>(xproj, prefix, hsh, log_A);
    }

    // GEMM2: y = hs @ C_w^T + x * D_param
    {
        dim3 grid(D_DIM / 128, M_TOTAL / 128);
        gemm2_hmma<<<grid, 256, SMEM2>>>(hsh, Cwh, Cwl, y, x, D_param);
    }

    final_state_kernel<<<1, N_DIM>>>(xproj, fs);
}

// round 10
// speedup vs baseline: 1.0253x; 1.0253x over previous
#include <cuda_runtime.h>
#include <cuda_bf16.h>
#include <cstdint>

#define B_DIM 8
#define L_DIM 4096
#define D_DIM 1024
#define N_DIM 128
#define M_TOTAL (B_DIM * L_DIM)   // 32768
#define CHUNK 64
#define NCHUNK (L_DIM / CHUNK)    // 64
#define TOT_CHUNKS (B_DIM * NCHUNK) // 512

// Scratch (no cudaMalloc allowed)
__device__ float g_xproj[(size_t)M_TOTAL * N_DIM];
__device__ float g_carry[TOT_CHUNKS * N_DIM];
__device__ float g_prefix[TOT_CHUNKS * N_DIM];
__device__ __nv_bfloat16 g_hsh[(size_t)M_TOTAL * N_DIM];
__device__ __nv_bfloat16 g_hsl[(size_t)M_TOTAL * N_DIM];
__device__ __nv_bfloat16 g_Bwh[N_DIM * D_DIM];
__device__ __nv_bfloat16 g_Bwl[N_DIM * D_DIM];
__device__ __nv_bfloat16 g_Cwh[D_DIM * N_DIM];
__device__ __nv_bfloat16 g_Cwl[D_DIM * N_DIM];

typedef unsigned long long u64;
typedef uint32_t u32;

__device__ __forceinline__ u32 smem_to_u32(const void* p) {
    u32 a;
    asm("{ .reg .u64 t; cvta.to.shared.u64 t, %1; cvt.u32.u64 %0, t; }"
        : "=r"(a) : "l"(p));
    return a;
}
__device__ __forceinline__ u32 swz(u32 o) { return o ^ ((o >> 3) & 0x70); }

__device__ __forceinline__ void ldsm4(u32* r, u32 addr) {
    asm volatile("ldmatrix.sync.aligned.m8n8.x4.shared.b16 {%0,%1,%2,%3}, [%4];"
                 : "=r"(r[0]), "=r"(r[1]), "=r"(r[2]), "=r"(r[3]) : "r"(addr));
}
__device__ __forceinline__ void mma16816(float* c, const u32* a, const u32* b) {
    asm volatile("mma.sync.aligned.m16n8k16.row.col.f32.bf16.bf16.f32 "
                 "{%0,%1,%2,%3}, {%4,%5,%6,%7}, {%8,%9}, {%0,%1,%2,%3};"
                 : "+f"(c[0]), "+f"(c[1]), "+f"(c[2]), "+f"(c[3])
                 : "r"(a[0]), "r"(a[1]), "r"(a[2]), "r"(a[3]),
                   "r"(b[0]), "r"(b[1]));
}
__device__ __forceinline__ u64 pack_bf16x4(float a, float b, float c, float d) {
    __nv_bfloat162 p0 = __floats2bfloat162_rn(a, b);
    __nv_bfloat162 p1 = __floats2bfloat162_rn(c, d);
    u32 lo = *(u32*)&p0, hi = *(u32*)&p1;
    return ((u64)hi << 32) | lo;
}
#define CP_ASYNC16(dst, src) \
    asm volatile("cp.async.cg.shared.global [%0], [%1], 16;" :: "r"(dst), "l"(src))
#define CP_COMMIT() asm volatile("cp.async.commit_group;")
#define CP_WAIT0() asm volatile("cp.async.wait_group 0;")
#define CP_WAIT1() asm volatile("cp.async.wait_group 1;")

// ───────── GEMM1: xproj = x @ B_w^T (A split in-kernel bf16 3-term, B presplit) ─────
// CTA 128x128, warp tile 64x32, KC=32 fp32, 2 stages, ONE barrier per chunk.
// Stage 32KB: A @0 (128 x [hi 64B | lo 64B]), B @16384 (same layout).
__global__ void __launch_bounds__(256, 2)
gemm1_hmma(const float* __restrict__ A,
           const __nv_bfloat16* __restrict__ Bwh, const __nv_bfloat16* __restrict__ Bwl,
           float* __restrict__ C)
{
    constexpr int KTOT = D_DIM;
    constexpr int KC = 32;
    constexpr int NC = KTOT / KC;      // 32
    constexpr int STAGE = 32768;

    extern __shared__ char dsm[];
    const u32 raw = smem_to_u32(dsm);
    const u32 base = (raw + 1023u) & ~1023u;
    char* dbase = dsm + (base - raw);

    const int tid  = threadIdx.x;
    const int lane = tid & 31;
    const int warp = tid >> 5;
    const int wr = warp & 1;
    const int wc = warp >> 1;
    const long row0 = (long)blockIdx.y * 128;

    const int r   = tid >> 1;
    const int hv  = tid & 1;
    const int cf0 = hv * 16;
    const float* Arow = A + (row0 + r) * (long)KTOT;
    const __nv_bfloat16* Bsrc = (hv ? Bwl : Bwh) + (size_t)r * KTOT;

    const int g  = lane >> 3;
    const int ln = lane & 7;
    const int rA = wr * 64 + (g & 1) * 8 + ln;
    const int cA = (g >> 1) * 16;
    const int rB = wc * 32 + (g >> 1) * 8 + ln;
    const int cB = (g & 1) * 16;

    float acc[4][4][4];
#pragma unroll
    for (int i = 0; i < 4; i++)
#pragma unroll
        for (int j = 0; j < 4; j++)
#pragma unroll
            for (int q = 0; q < 4; q++) acc[i][j][q] = 0.0f;

    // prologue: prefetch A fp32 chunk0 into regs; issue B chunk0
    float4 pa[4];
#pragma unroll
    for (int q = 0; q < 4; q++) pa[q] = *(const float4*)(Arow + cf0 + q * 4);
    {
        const u32 bdst = base + 16384;
#pragma unroll
        for (int i = 0; i < 4; i++)
            CP_ASYNC16(bdst + swz((u32)r * 128 + hv * 64 + i * 16), Bsrc + i * 8);
        CP_COMMIT();
    }

    for (int c = 0; c < NC; c++) {
        const int s = c & 1;
        char* bufA = dbase + s * STAGE;

        // convert A chunk c into stage s (writes A-parity s; MMA(c-1) reads parity s^1 — safe)
#pragma unroll
        for (int q = 0; q < 4; q++) {
            float4 v = pa[q];
            float hx = __bfloat162float(__float2bfloat16(v.x));
            float hy = __bfloat162float(__float2bfloat16(v.y));
            float hz = __bfloat162float(__float2bfloat16(v.z));
            float hw = __bfloat162float(__float2bfloat16(v.w));
            const u32 cbyte = (u32)(cf0 + q * 4) * 2;
            *(u64*)(bufA + swz((u32)r * 128 + cbyte))      = pack_bf16x4(hx, hy, hz, hw);
            *(u64*)(bufA + swz((u32)r * 128 + 64 + cbyte)) =
                pack_bf16x4(v.x - hx, v.y - hy, v.z - hz, v.w - hw);
        }
        CP_WAIT0();          // B(c) arrived (only that group can be outstanding here)
        __syncthreads();     // convert(c) + B(c) visible; all warps done with MMA(c-1)

        // issue B(c+1) AFTER barrier: its stage parity equals MMA(c-1)'s — barrier makes it safe
        if (c + 1 < NC) {
            const u32 bdst = base + ((c + 1) & 1) * STAGE + 16384;
            const __nv_bfloat16* src = Bsrc + (c + 1) * KC;
#pragma unroll
            for (int i = 0; i < 4; i++)
                CP_ASYNC16(bdst + swz((u32)r * 128 + hv * 64 + i * 16), src + i * 8);
            CP_COMMIT();
            // prefetch A fp32 chunk c+1 (overlaps MMA)
            const int kn = (c + 1) * KC;
#pragma unroll
            for (int q = 0; q < 4; q++)
                pa[q] = *(const float4*)(Arow + kn + cf0 + q * 4);
        }

        const u32 ab = base + s * STAGE;
        const u32 bb = ab + 16384;
#pragma unroll
        for (int ks = 0; ks < 2; ks++) {
            const u32 kA = (u32)(ks * 32 + cA);
            const u32 kB = (u32)(ks * 32 + cB);
            u32 ah[4][4], al[4][4], bf[2][4];
#pragma unroll
            for (int mt = 0; mt < 4; mt++)
                ldsm4(ah[mt], ab + swz((u32)(rA + mt * 16) * 128 + kA));
#pragma unroll
            for (int p = 0; p < 2; p++)
                ldsm4(bf[p], bb + swz((u32)(rB + p * 16) * 128 + kB));
#pragma unroll
            for (int mt = 0; mt < 4; mt++)
#pragma unroll
                for (int nt = 0; nt < 4; nt++)
                    mma16816(acc[mt][nt], ah[mt], &bf[nt >> 1][(nt & 1) * 2]);
#pragma unroll
            for (int mt = 0; mt < 4; mt++)
                ldsm4(al[mt], ab + swz((u32)(rA + mt * 16) * 128 + 64 + kA));
#pragma unroll
            for (int mt = 0; mt < 4; mt++)
#pragma unroll
                for (int nt = 0; nt < 4; nt++)
                    mma16816(acc[mt][nt], al[mt], &bf[nt >> 1][(nt & 1) * 2]);
#pragma unroll
            for (int p = 0; p < 2; p++)
                ldsm4(bf[p], bb + swz((u32)(rB + p * 16) * 128 + 64 + kB));
#pragma unroll
            for (int mt = 0; mt < 4; mt++)
#pragma unroll
                for (int nt = 0; nt < 4; nt++)
                    mma16816(acc[mt][nt], ah[mt], &bf[nt >> 1][(nt & 1) * 2]);
        }
        // no end barrier: next convert writes A-parity s^1; safe via next mid-barrier argument
    }

    const int er = lane >> 2;
    const int ec = (lane & 3) * 2;
#pragma unroll
    for (int mt = 0; mt < 4; mt++)
#pragma unroll
        for (int nt = 0; nt < 4; nt++) {
            const long m = row0 + wr * 64 + mt * 16 + er;
            const long n = wc * 32 + nt * 8 + ec;
            *(float2*)(C + m * (long)N_DIM + n) = make_float2(acc[mt][nt][0], acc[mt][nt][1]);
            *(float2*)(C + (m + 8) * (long)N_DIM + n) = make_float2(acc[mt][nt][2], acc[mt][nt][3]);
        }
}

// ───────── GEMM2: y = hs @ C_w^T + x*Dp. All bf16 presplit, 3-stage, 1 barrier/chunk ─────
__global__ void __launch_bounds__(256, 2)
gemm2_hmma(const __nv_bfloat16* __restrict__ hsh, const __nv_bfloat16* __restrict__ hsl,
           const __nv_bfloat16* __restrict__ Cwh, const __nv_bfloat16* __restrict__ Cwl,
           float* __restrict__ C,
           const float* __restrict__ X, const float* __restrict__ Dp)
{
    constexpr int NVC = 6;
    constexpr int STAGE = 32768;

    extern __shared__ char dsm[];
    const u32 raw = smem_to_u32(dsm);
    const u32 base = (raw + 1023u) & ~1023u;

    const int tid  = threadIdx.x;
    const int lane = tid & 31;
    const int warp = tid >> 5;
    const int wr = warp & 1;
    const int wc = warp >> 1;
    const long row0 = (long)blockIdx.y * 128;
    const long col0 = (long)blockIdx.x * 128;

    const int r2 = tid >> 1;
    const int hv = tid & 1;

    const int g  = lane >> 3;
    const int ln = lane & 7;
    const int rA = wr * 64 + (g & 1) * 8 + ln;
    const int cA = (g >> 1) * 16;
    const int rB = wc * 32 + (g >> 1) * 8 + ln;
    const int cB = (g & 1) * 16;

    float acc[4][4][4];
#pragma unroll
    for (int i = 0; i < 4; i++)
#pragma unroll
        for (int j = 0; j < 4; j++)
#pragma unroll
            for (int q = 0; q < 4; q++) acc[i][j][q] = 0.0f;

    auto issue = [&](int vc) {
        const u32 sb = base + (vc % 3) * STAGE;
        const int t  = vc >> 1;
        const int kk = (vc & 1) * 64;
        const __nv_bfloat16* As = (t == 1) ? hsl : hsh;
        const __nv_bfloat16* Bs = (t == 2) ? Cwl : Cwh;
        const __nv_bfloat16* asrc = As + (row0 + r2) * (long)N_DIM + kk + hv * 32;
        const __nv_bfloat16* bsrc = Bs + (col0 + r2) * (long)N_DIM + kk + hv * 32;
#pragma unroll
        for (int i = 0; i < 4; i++)
            CP_ASYNC16(sb + swz((u32)r2 * 128 + hv * 64 + i * 16), asrc + i * 8);
#pragma unroll
        for (int i = 0; i < 4; i++)
            CP_ASYNC16(sb + 16384 + swz((u32)r2 * 128 + hv * 64 + i * 16), bsrc + i * 8);
        CP_COMMIT();
    };

    issue(0);
    issue(1);

    for (int vc = 0; vc < NVC; vc++) {
        if (vc + 1 < NVC) { CP_WAIT1(); } else { CP_WAIT0(); }
        __syncthreads();                  // stage vc visible; MMA(vc-1) done everywhere
        if (vc + 2 < NVC) issue(vc + 2);  // targets stage (vc-1)%3: safe post-barrier

        const u32 ab = base + (vc % 3) * STAGE;
        const u32 bb = ab + 16384;
#pragma unroll
        for (int ks = 0; ks < 4; ks++) {
            const u32 kA = (u32)(ks * 32 + cA);
            const u32 kB = (u32)(ks * 32 + cB);
            u32 ah[4][4], bf[2][4];
#pragma unroll
            for (int mt = 0; mt < 4; mt++)
                ldsm4(ah[mt], ab + swz((u32)(rA + mt * 16) * 128 + kA));
#pragma unroll
            for (int p = 0; p < 2; p++)
                ldsm4(bf[p], bb + swz((u32)(rB + p * 16) * 128 + kB));
#pragma unroll
            for (int mt = 0; mt < 4; mt++)
#pragma unroll
                for (int nt = 0; nt < 4; nt++)
                    mma16816(acc[mt][nt], ah[mt], &bf[nt >> 1][(nt & 1) * 2]);
        }
    }

    const int er = lane >> 2;
    const int ec = (lane & 3) * 2;
#pragma unroll
    for (int mt = 0; mt < 4; mt++)
#pragma unroll
        for (int nt = 0; nt < 4; nt++) {
            const long m = row0 + wr * 64 + mt * 16 + er;
            const long n = col0 + wc * 32 + nt * 8 + ec;
            float2 dv = *(const float2*)(Dp + n);
            float2 x0 = *(const float2*)(X + m * (long)D_DIM + n);
            float2 x1 = *(const float2*)(X + (m + 8) * (long)D_DIM + n);
            float2 o0, o1;
            o0.x = fmaf(x0.x, dv.x, acc[mt][nt][0]);
            o0.y = fmaf(x0.y, dv.y, acc[mt][nt][1]);
            o1.x = fmaf(x1.x, dv.x, acc[mt][nt][2]);
            o1.y = fmaf(x1.y, dv.y, acc[mt][nt][3]);
            *(float2*)(C + m * (long)D_DIM + n) = o0;
            *(float2*)(C + (m + 8) * (long)D_DIM + n) = o1;
        }
}

// ───────── fused weight presplit: B_w then C_w in one launch ─────────
__global__ void split_both_kernel(const float* __restrict__ Bw, const float* __restrict__ Cw,
                                  __nv_bfloat16* __restrict__ Bwh, __nv_bfloat16* __restrict__ Bwl,
                                  __nv_bfloat16* __restrict__ Cwh, __nv_bfloat16* __restrict__ Cwl)
{
    const int nb = N_DIM * D_DIM;
    int i = blockIdx.x * blockDim.x + threadIdx.x;
    const float* src;
    __nv_bfloat16 *dh, *dl;
    int j;
    if (i < nb) { src = Bw; dh = Bwh; dl = Bwl; j = i; }
    else        { src = Cw; dh = Cwh; dl = Cwl; j = i - nb; if (j >= D_DIM * N_DIM) return; }
    float v = src[j];
    __nv_bfloat16 h = __float2bfloat16(v);
    dh[j] = h;
    dl[j] = __float2bfloat16(v - __bfloat162float(h));
}

// ───────── scan: 3 passes, CHUNK=64; final_state fused into carry_scan ─────────
__global__ void __launch_bounds__(128)
scan_carry(const float* __restrict__ xproj, float* __restrict__ carry,
           const float* __restrict__ log_A)
{
    int n = threadIdx.x;
    int chunk = blockIdx.x;
    int b = blockIdx.y;
    float A = expf(log_A[n]);
    const float* src = xproj + ((size_t)b * L_DIM + (size_t)chunk * CHUNK) * N_DIM + n;
    float h = 0.0f;
#pragma unroll 8
    for (int i = 0; i < CHUNK; i++)
        h = fmaf(A, h, src[(size_t)i * N_DIM]);
    carry[(b * NCHUNK + chunk) * N_DIM + n] = h;
}

__global__ void __launch_bounds__(128)
carry_scan(const float* __restrict__ carry, float* __restrict__ prefix,
           const float* __restrict__ log_A,
           const float* __restrict__ xproj, float* __restrict__ fs)
{
    int n = threadIdx.x;
    int b = blockIdx.x;
    float Ac = expf((float)CHUNK * log_A[n]);
    float h = 0.0f;
#pragma unroll
    for (int c = 0; c < NCHUNK; c++) {
        prefix[(b * NCHUNK + c) * N_DIM + n] = h;   // exclusive
        h = fmaf(Ac, h, carry[(b * NCHUNK + c) * N_DIM + n]);
    }
    // fused final_state: fs[b][n] = mean over batches of xproj[b', L-1, n]
    float s = 0.0f;
#pragma unroll
    for (int bb = 0; bb < B_DIM; bb++)
        s += xproj[((size_t)bb * L_DIM + (L_DIM - 1)) * N_DIM + n];
    fs[b * N_DIM + n] = s * (1.0f / B_DIM);
}

__global__ void __launch_bounds__(128)
scan_split(const float* __restrict__ xproj, const float* __restrict__ prefix,
           __nv_bfloat16* __restrict__ hsh, __nv_bfloat16* __restrict__ hsl,
           const float* __restrict__ log_A)
{
    int n = threadIdx.x;
    int chunk = blockIdx.x;
    int b = blockIdx.y;
    float A = expf(log_A[n]);
    size_t bo = ((size_t)b * L_DIM + (size_t)chunk * CHUNK) * N_DIM + n;
    const float* src = xproj + bo;
    float h = prefix[(b * NCHUNK + chunk) * N_DIM + n];
#pragma unroll 8
    for (int i = 0; i < CHUNK; i++) {
        h = fmaf(A, h, src[(size_t)i * N_DIM]);
        __nv_bfloat16 hb = __float2bfloat16(h);
        hsh[bo + (size_t)i * N_DIM] = hb;
        hsl[bo + (size_t)i * N_DIM] = __float2bfloat16(h - __bfloat162float(hb));
    }
}

// ─────────────────────────────── launch ───────────────────────────────
extern "C" void kernel_launch(void* const* d_in, const int* in_sizes, int n_in,
                              void* d_out, int out_size)
{
    const float* x       = (const float*)d_in[0];
    const float* B_w     = (const float*)d_in[1];
    const float* C_w     = (const float*)d_in[2];
    const float* log_A   = (const float*)d_in[3];
    const float* D_param = (const float*)d_in[4];

    float* y  = (float*)d_out;
    float* fs = y + ((size_t)out_size - (size_t)B_DIM * N_DIM);

    float *xproj, *carry, *prefix;
    __nv_bfloat16 *hsh, *hsl, *Bwh, *Bwl, *Cwh, *Cwl;
    cudaGetSymbolAddress((void**)&xproj, g_xproj);
    cudaGetSymbolAddress((void**)&carry, g_carry);
    cudaGetSymbolAddress((void**)&prefix, g_prefix);
    cudaGetSymbolAddress((void**)&hsh, g_hsh);
    cudaGetSymbolAddress((void**)&hsl, g_hsl);
    cudaGetSymbolAddress((void**)&Bwh, g_Bwh);
    cudaGetSymbolAddress((void**)&Bwl, g_Bwl);
    cudaGetSymbolAddress((void**)&Cwh, g_Cwh);
    cudaGetSymbolAddress((void**)&Cwl, g_Cwl);

    const int SMEM1 = 2 * 32768 + 1024;   // 66560
    const int SMEM2 = 3 * 32768 + 1024;   // 99328
    cudaFuncSetAttribute(gemm1_hmma, cudaFuncAttributeMaxDynamicSharedMemorySize, SMEM1);
    cudaFuncSetAttribute(gemm2_hmma, cudaFuncAttributeMaxDynamicSharedMemorySize, SMEM2);

    split_both_kernel<<<(2 * N_DIM * D_DIM + 255) / 256, 256>>>(B_w, C_w, Bwh, Bwl, Cwh, Cwl);

    // GEMM1: xproj = x @ B_w^T
    {
        dim3 grid(1, M_TOTAL / 128);
        gemm1_hmma<<<grid, 256, SMEM1>>>(x, Bwh, Bwl, xproj);
    }

    // scan: carries -> prefix(+final_state) -> fixed split hs
    {
        dim3 grid(NCHUNK, B_DIM);
        scan_carry<<<grid, 128>>>(xproj, carry, log_A);
        carry_scan<<<B_DIM, 128>>>(carry, prefix, log_A, xproj, fs);
        scan_split<<<grid, 128>>>(xproj, prefix, hsh, hsl, log_A);
    }

    // GEMM2: y = hs @ C_w^T + x * D_param
    {
        dim3 grid(D_DIM / 128, M_TOTAL / 128);
        gemm2_hmma<<<grid, 256, SMEM2>>>(hsh, hsl, Cwh, Cwl, y, x, D_param);
    }
}

// round 11
// speedup vs baseline: 1.1027x; 1.0755x over previous
#include <cuda_runtime.h>
#include <cuda_bf16.h>
#include <cstdint>

#define B_DIM 8
#define L_DIM 4096
#define D_DIM 1024
#define N_DIM 128
#define M_TOTAL (B_DIM * L_DIM)   // 32768
#define CHUNK 64
#define NCHUNK (L_DIM / CHUNK)    // 64
#define TOT_CHUNKS (B_DIM * NCHUNK) // 512

// Scratch (no cudaMalloc allowed)
__device__ float g_xproj[(size_t)M_TOTAL * N_DIM];
__device__ float g_carry[TOT_CHUNKS * N_DIM];
__device__ float g_prefix[TOT_CHUNKS * N_DIM];
__device__ __nv_bfloat16 g_hsh[(size_t)M_TOTAL * N_DIM];
__device__ __nv_bfloat16 g_hsl[(size_t)M_TOTAL * N_DIM];
__device__ __nv_bfloat16 g_Bwh[N_DIM * D_DIM];
__device__ __nv_bfloat16 g_Bwl[N_DIM * D_DIM];
__device__ __nv_bfloat16 g_Cwh[D_DIM * N_DIM];
__device__ __nv_bfloat16 g_Cwl[D_DIM * N_DIM];

typedef unsigned long long u64;
typedef uint32_t u32;

__device__ __forceinline__ u32 smem_to_u32(const void* p) {
    u32 a;
    asm("{ .reg .u64 t; cvta.to.shared.u64 t, %1; cvt.u32.u64 %0, t; }"
        : "=r"(a) : "l"(p));
    return a;
}
__device__ __forceinline__ u32 swz(u32 o) { return o ^ ((o >> 3) & 0x70); }

__device__ __forceinline__ void ldsm4(u32* r, u32 addr) {
    asm volatile("ldmatrix.sync.aligned.m8n8.x4.shared.b16 {%0,%1,%2,%3}, [%4];"
                 : "=r"(r[0]), "=r"(r[1]), "=r"(r[2]), "=r"(r[3]) : "r"(addr));
}
__device__ __forceinline__ void mma16816(float* c, const u32* a, const u32* b) {
    asm volatile("mma.sync.aligned.m16n8k16.row.col.f32.bf16.bf16.f32 "
                 "{%0,%1,%2,%3}, {%4,%5,%6,%7}, {%8,%9}, {%0,%1,%2,%3};"
                 : "+f"(c[0]), "+f"(c[1]), "+f"(c[2]), "+f"(c[3])
                 : "r"(a[0]), "r"(a[1]), "r"(a[2]), "r"(a[3]),
                   "r"(b[0]), "r"(b[1]));
}
__device__ __forceinline__ u64 pack_bf16x4(float a, float b, float c, float d) {
    __nv_bfloat162 p0 = __floats2bfloat162_rn(a, b);
    __nv_bfloat162 p1 = __floats2bfloat162_rn(c, d);
    u32 lo = *(u32*)&p0, hi = *(u32*)&p1;
    return ((u64)hi << 32) | lo;
}
#define CP_ASYNC16(dst, src) \
    asm volatile("cp.async.cg.shared.global [%0], [%1], 16;" :: "r"(dst), "l"(src))
#define CP_COMMIT() asm volatile("cp.async.commit_group;")
#define CP_WAIT0() asm volatile("cp.async.wait_group 0;")
#define CP_WAIT1() asm volatile("cp.async.wait_group 1;")

// ───────── GEMM1: xproj = x @ B_w^T (R6 structure — no reg cap, 2 barriers/chunk) ─────
// A (x) split in-kernel to bf16 hi/lo, B presplit bf16 via cp.async.
// CTA 128x128, warp tile 64x32, KC=32 fp32, double buffer.
__global__ void __launch_bounds__(256)
gemm1_hmma(const float* __restrict__ A,
           const __nv_bfloat16* __restrict__ Bwh, const __nv_bfloat16* __restrict__ Bwl,
           float* __restrict__ C)
{
    constexpr int KTOT = D_DIM;
    constexpr int KC = 32;
    constexpr int NC = KTOT / KC;      // 32
    constexpr int STAGE = 32768;       // A 16KB + B 16KB

    extern __shared__ char dsm[];
    const u32 raw = smem_to_u32(dsm);
    const u32 base = (raw + 1023u) & ~1023u;
    char* dbase = dsm + (base - raw);

    const int tid  = threadIdx.x;
    const int lane = tid & 31;
    const int warp = tid >> 5;
    const int wr = warp & 1;
    const int wc = warp >> 1;
    const long row0 = (long)blockIdx.y * 128;

    const int r   = tid >> 1;
    const int hv  = tid & 1;
    const int cf0 = hv * 16;
    const float* Arow = A + (row0 + r) * (long)KTOT;
    const __nv_bfloat16* Bsrc = (hv ? Bwl : Bwh) + (size_t)r * KTOT;

    const int g  = lane >> 3;
    const int ln = lane & 7;
    const int rA = wr * 64 + (g & 1) * 8 + ln;
    const int cA = (g >> 1) * 16;
    const int rB = wc * 32 + (g >> 1) * 8 + ln;
    const int cB = (g & 1) * 16;

    float acc[4][4][4];
#pragma unroll
    for (int i = 0; i < 4; i++)
#pragma unroll
        for (int j = 0; j < 4; j++)
#pragma unroll
            for (int q = 0; q < 4; q++) acc[i][j][q] = 0.0f;

    // prologue: prefetch A fp32 chunk0; issue B chunk0
    float4 pa[4];
#pragma unroll
    for (int q = 0; q < 4; q++) pa[q] = *(const float4*)(Arow + cf0 + q * 4);
    {
        const u32 bdst = base + 16384;
#pragma unroll
        for (int i = 0; i < 4; i++)
            CP_ASYNC16(bdst + swz((u32)r * 128 + hv * 64 + i * 16), Bsrc + i * 8);
        CP_COMMIT();
    }

    for (int c = 0; c < NC; c++) {
        const int s = c & 1;
        char* bufA = dbase + s * STAGE;

        // convert A chunk c (from prefetched regs) into stage s
#pragma unroll
        for (int q = 0; q < 4; q++) {
            float4 v = pa[q];
            float hx = __bfloat162float(__float2bfloat16(v.x));
            float hy = __bfloat162float(__float2bfloat16(v.y));
            float hz = __bfloat162float(__float2bfloat16(v.z));
            float hw = __bfloat162float(__float2bfloat16(v.w));
            const u32 cbyte = (u32)(cf0 + q * 4) * 2;
            *(u64*)(bufA + swz((u32)r * 128 + cbyte))      = pack_bf16x4(hx, hy, hz, hw);
            *(u64*)(bufA + swz((u32)r * 128 + 64 + cbyte)) =
                pack_bf16x4(v.x - hx, v.y - hy, v.z - hz, v.w - hw);
        }
        // issue B chunk c+1 into other stage
        if (c + 1 < NC) {
            const u32 bdst = base + ((c + 1) & 1) * STAGE + 16384;
            const __nv_bfloat16* src = Bsrc + (c + 1) * KC;
#pragma unroll
            for (int i = 0; i < 4; i++)
                CP_ASYNC16(bdst + swz((u32)r * 128 + hv * 64 + i * 16), src + i * 8);
            CP_COMMIT();
            CP_WAIT1();
        } else {
            CP_WAIT0();
        }
        __syncthreads();

        // prefetch A fp32 chunk c+1 (overlaps MMA)
        if (c + 1 < NC) {
            const int kn = (c + 1) * KC;
#pragma unroll
            for (int q = 0; q < 4; q++)
                pa[q] = *(const float4*)(Arow + kn + cf0 + q * 4);
        }

        // MMA on stage s: chains AhBh, AlBh, AhBl
        const u32 ab = base + s * STAGE;
        const u32 bb = ab + 16384;
#pragma unroll
        for (int ks = 0; ks < 2; ks++) {
            const u32 kA = (u32)(ks * 32 + cA);
            const u32 kB = (u32)(ks * 32 + cB);
            u32 ah[4][4], al[4][4], bf[2][4];
#pragma unroll
            for (int mt = 0; mt < 4; mt++)
                ldsm4(ah[mt], ab + swz((u32)(rA + mt * 16) * 128 + kA));
#pragma unroll
            for (int p = 0; p < 2; p++)
                ldsm4(bf[p], bb + swz((u32)(rB + p * 16) * 128 + kB));
#pragma unroll
            for (int mt = 0; mt < 4; mt++)
#pragma unroll
                for (int nt = 0; nt < 4; nt++)
                    mma16816(acc[mt][nt], ah[mt], &bf[nt >> 1][(nt & 1) * 2]);
#pragma unroll
            for (int mt = 0; mt < 4; mt++)
                ldsm4(al[mt], ab + swz((u32)(rA + mt * 16) * 128 + 64 + kA));
#pragma unroll
            for (int mt = 0; mt < 4; mt++)
#pragma unroll
                for (int nt = 0; nt < 4; nt++)
                    mma16816(acc[mt][nt], al[mt], &bf[nt >> 1][(nt & 1) * 2]);
#pragma unroll
            for (int p = 0; p < 2; p++)
                ldsm4(bf[p], bb + swz((u32)(rB + p * 16) * 128 + 64 + kB));
#pragma unroll
            for (int mt = 0; mt < 4; mt++)
#pragma unroll
                for (int nt = 0; nt < 4; nt++)
                    mma16816(acc[mt][nt], ah[mt], &bf[nt >> 1][(nt & 1) * 2]);
        }
        __syncthreads();
    }

    const int er = lane >> 2;
    const int ec = (lane & 3) * 2;
#pragma unroll
    for (int mt = 0; mt < 4; mt++)
#pragma unroll
        for (int nt = 0; nt < 4; nt++) {
            const long m = row0 + wr * 64 + mt * 16 + er;
            const long n = wc * 32 + nt * 8 + ec;
            *(float2*)(C + m * (long)N_DIM + n) = make_float2(acc[mt][nt][0], acc[mt][nt][1]);
            *(float2*)(C + (m + 8) * (long)N_DIM + n) = make_float2(acc[mt][nt][2], acc[mt][nt][3]);
        }
}

// ───────── GEMM2: y = hs @ C_w^T + x*Dp (R6 structure — 3-stage, 2 barriers/chunk) ─────
__global__ void __launch_bounds__(256, 2)
gemm2_hmma(const __nv_bfloat16* __restrict__ hsh, const __nv_bfloat16* __restrict__ hsl,
           const __nv_bfloat16* __restrict__ Cwh, const __nv_bfloat16* __restrict__ Cwl,
           float* __restrict__ C,
           const float* __restrict__ X, const float* __restrict__ Dp)
{
    constexpr int NVC = 6;
    constexpr int STAGE = 32768;

    extern __shared__ char dsm[];
    const u32 raw = smem_to_u32(dsm);
    const u32 base = (raw + 1023u) & ~1023u;

    const int tid  = threadIdx.x;
    const int lane = tid & 31;
    const int warp = tid >> 5;
    const int wr = warp & 1;
    const int wc = warp >> 1;
    const long row0 = (long)blockIdx.y * 128;
    const long col0 = (long)blockIdx.x * 128;

    const int r2 = tid >> 1;
    const int hv = tid & 1;

    const int g  = lane >> 3;
    const int ln = lane & 7;
    const int rA = wr * 64 + (g & 1) * 8 + ln;
    const int cA = (g >> 1) * 16;
    const int rB = wc * 32 + (g >> 1) * 8 + ln;
    const int cB = (g & 1) * 16;

    float acc[4][4][4];
#pragma unroll
    for (int i = 0; i < 4; i++)
#pragma unroll
        for (int j = 0; j < 4; j++)
#pragma unroll
            for (int q = 0; q < 4; q++) acc[i][j][q] = 0.0f;

    auto issue = [&](int vc) {
        const u32 sb = base + (vc % 3) * STAGE;
        const int t  = vc >> 1;
        const int kk = (vc & 1) * 64;
        const __nv_bfloat16* As = (t == 1) ? hsl : hsh;
        const __nv_bfloat16* Bs = (t == 2) ? Cwl : Cwh;
        const __nv_bfloat16* asrc = As + (row0 + r2) * (long)N_DIM + kk + hv * 32;
        const __nv_bfloat16* bsrc = Bs + (col0 + r2) * (long)N_DIM + kk + hv * 32;
#pragma unroll
        for (int i = 0; i < 4; i++)
            CP_ASYNC16(sb + swz((u32)r2 * 128 + hv * 64 + i * 16), asrc + i * 8);
#pragma unroll
        for (int i = 0; i < 4; i++)
            CP_ASYNC16(sb + 16384 + swz((u32)r2 * 128 + hv * 64 + i * 16), bsrc + i * 8);
        CP_COMMIT();
    };

    issue(0);
    issue(1);

    for (int vc = 0; vc < NVC; vc++) {
        if (vc + 1 < NVC) { CP_WAIT1(); } else { CP_WAIT0(); }
        __syncthreads();
        if (vc + 2 < NVC) issue(vc + 2);

        const u32 ab = base + (vc % 3) * STAGE;
        const u32 bb = ab + 16384;
#pragma unroll
        for (int ks = 0; ks < 4; ks++) {
            const u32 kA = (u32)(ks * 32 + cA);
            const u32 kB = (u32)(ks * 32 + cB);
            u32 ah[4][4], bf[2][4];
#pragma unroll
            for (int mt = 0; mt < 4; mt++)
                ldsm4(ah[mt], ab + swz((u32)(rA + mt * 16) * 128 + kA));
#pragma unroll
            for (int p = 0; p < 2; p++)
                ldsm4(bf[p], bb + swz((u32)(rB + p * 16) * 128 + kB));
#pragma unroll
            for (int mt = 0; mt < 4; mt++)
#pragma unroll
                for (int nt = 0; nt < 4; nt++)
                    mma16816(acc[mt][nt], ah[mt], &bf[nt >> 1][(nt & 1) * 2]);
        }
        __syncthreads();
    }

    const int er = lane >> 2;
    const int ec = (lane & 3) * 2;
#pragma unroll
    for (int mt = 0; mt < 4; mt++)
#pragma unroll
        for (int nt = 0; nt < 4; nt++) {
            const long m = row0 + wr * 64 + mt * 16 + er;
            const long n = col0 + wc * 32 + nt * 8 + ec;
            float2 dv = *(const float2*)(Dp + n);
            float2 x0 = *(const float2*)(X + m * (long)D_DIM + n);
            float2 x1 = *(const float2*)(X + (m + 8) * (long)D_DIM + n);
            float2 o0, o1;
            o0.x = fmaf(x0.x, dv.x, acc[mt][nt][0]);
            o0.y = fmaf(x0.y, dv.y, acc[mt][nt][1]);
            o1.x = fmaf(x1.x, dv.x, acc[mt][nt][2]);
            o1.y = fmaf(x1.y, dv.y, acc[mt][nt][3]);
            *(float2*)(C + m * (long)D_DIM + n) = o0;
            *(float2*)(C + (m + 8) * (long)D_DIM + n) = o1;
        }
}

// ───────── fused weight presplit: B_w and C_w in one launch ─────────
__global__ void split_both_kernel(const float* __restrict__ Bw, const float* __restrict__ Cw,
                                  __nv_bfloat16* __restrict__ Bwh, __nv_bfloat16* __restrict__ Bwl,
                                  __nv_bfloat16* __restrict__ Cwh, __nv_bfloat16* __restrict__ Cwl)
{
    const int nb = N_DIM * D_DIM;
    int i = blockIdx.x * blockDim.x + threadIdx.x;
    const float* src;
    __nv_bfloat16 *dh, *dl;
    int j;
    if (i < nb) { src = Bw; dh = Bwh; dl = Bwl; j = i; }
    else        { src = Cw; dh = Cwh; dl = Cwl; j = i - nb; if (j >= D_DIM * N_DIM) return; }
    float v = src[j];
    __nv_bfloat16 h = __float2bfloat16(v);
    dh[j] = h;
    dl[j] = __float2bfloat16(v - __bfloat162float(h));
}

// ───────── scan: 3 passes, CHUNK=64; final_state fused into carry_scan ─────────
__global__ void __launch_bounds__(128)
scan_carry(const float* __restrict__ xproj, float* __restrict__ carry,
           const float* __restrict__ log_A)
{
    int n = threadIdx.x;
    int chunk = blockIdx.x;
    int b = blockIdx.y;
    float A = expf(log_A[n]);
    const float* src = xproj + ((size_t)b * L_DIM + (size_t)chunk * CHUNK) * N_DIM + n;
    float h = 0.0f;
#pragma unroll 8
    for (int i = 0; i < CHUNK; i++)
        h = fmaf(A, h, src[(size_t)i * N_DIM]);
    carry[(b * NCHUNK + chunk) * N_DIM + n] = h;
}

__global__ void __launch_bounds__(128)
carry_scan(const float* __restrict__ carry, float* __restrict__ prefix,
           const float* __restrict__ log_A,
           const float* __restrict__ xproj, float* __restrict__ fs)
{
    int n = threadIdx.x;
    int b = blockIdx.x;
    float Ac = expf((float)CHUNK * log_A[n]);
    float h = 0.0f;
#pragma unroll
    for (int c = 0; c < NCHUNK; c++) {
        prefix[(b * NCHUNK + c) * N_DIM + n] = h;   // exclusive
        h = fmaf(Ac, h, carry[(b * NCHUNK + c) * N_DIM + n]);
    }
    // fused final_state: identical for every b (mean over batches, broadcast)
    float s = 0.0f;
#pragma unroll
    for (int bb = 0; bb < B_DIM; bb++)
        s += xproj[((size_t)bb * L_DIM + (L_DIM - 1)) * N_DIM + n];
    fs[b * N_DIM + n] = s * (1.0f / B_DIM);
}

__global__ void __launch_bounds__(128)
scan_split(const float* __restrict__ xproj, const float* __restrict__ prefix,
           __nv_bfloat16* __restrict__ hsh, __nv_bfloat16* __restrict__ hsl,
           const float* __restrict__ log_A)
{
    int n = threadIdx.x;
    int chunk = blockIdx.x;
    int b = blockIdx.y;
    float A = expf(log_A[n]);
    size_t bo = ((size_t)b * L_DIM + (size_t)chunk * CHUNK) * N_DIM + n;
    const float* src = xproj + bo;
    float h = prefix[(b * NCHUNK + chunk) * N_DIM + n];
#pragma unroll 8
    for (int i = 0; i < CHUNK; i++) {
        h = fmaf(A, h, src[(size_t)i * N_DIM]);
        __nv_bfloat16 hb = __float2bfloat16(h);
        hsh[bo + (size_t)i * N_DIM] = hb;
        hsl[bo + (size_t)i * N_DIM] = __float2bfloat16(h - __bfloat162float(hb));
    }
}

// ─────────────────────────────── launch ───────────────────────────────
extern "C" void kernel_launch(void* const* d_in, const int* in_sizes, int n_in,
                              void* d_out, int out_size)
{
    const float* x       = (const float*)d_in[0];
    const float* B_w     = (const float*)d_in[1];
    const float* C_w     = (const float*)d_in[2];
    const float* log_A   = (const float*)d_in[3];
    const float* D_param = (const float*)d_in[4];

    float* y  = (float*)d_out;
    float* fs = y + ((size_t)out_size - (size_t)B_DIM * N_DIM);

    float *xproj, *carry, *prefix;
    __nv_bfloat16 *hsh, *hsl, *Bwh, *Bwl, *Cwh, *Cwl;
    cudaGetSymbolAddress((void**)&xproj, g_xproj);
    cudaGetSymbolAddress((void**)&carry, g_carry);
    cudaGetSymbolAddress((void**)&prefix, g_prefix);
    cudaGetSymbolAddress((void**)&hsh, g_hsh);
    cudaGetSymbolAddress((void**)&hsl, g_hsl);
    cudaGetSymbolAddress((void**)&Bwh, g_Bwh);
    cudaGetSymbolAddress((void**)&Bwl, g_Bwl);
    cudaGetSymbolAddress((void**)&Cwh, g_Cwh);
    cudaGetSymbolAddress((void**)&Cwl, g_Cwl);

    const int SMEM1 = 2 * 32768 + 1024;   // 66560
    const int SMEM2 = 3 * 32768 + 1024;   // 99328
    cudaFuncSetAttribute(gemm1_hmma, cudaFuncAttributeMaxDynamicSharedMemorySize, SMEM1);
    cudaFuncSetAttribute(gemm2_hmma, cudaFuncAttributeMaxDynamicSharedMemorySize, SMEM2);

    split_both_kernel<<<(2 * N_DIM * D_DIM + 255) / 256, 256>>>(B_w, C_w, Bwh, Bwl, Cwh, Cwl);

    // GEMM1: xproj = x @ B_w^T
    {
        dim3 grid(1, M_TOTAL / 128);
        gemm1_hmma<<<grid, 256, SMEM1>>>(x, Bwh, Bwl, xproj);
    }

    // scan: carries -> prefix(+final_state) -> fixed split hs
    {
        dim3 grid(NCHUNK, B_DIM);
        scan_carry<<<grid, 128>>>(xproj, carry, log_A);
        carry_scan<<<B_DIM, 128>>>(carry, prefix, log_A, xproj, fs);
        scan_split<<<grid, 128>>>(xproj, prefix, hsh, hsl, log_A);
    }

    // GEMM2: y = hs @ C_w^T + x * D_param
    {
        dim3 grid(D_DIM / 128, M_TOTAL / 128);
        gemm2_hmma<<<grid, 256, SMEM2>>>(hsh, hsl, Cwh, Cwl, y, x, D_param);
    }
}

// round 12
// speedup vs baseline: 1.1322x; 1.0268x over previous
#include <cuda_runtime.h>
#include <cuda_bf16.h>
#include <cstdint>

#define B_DIM 8
#define L_DIM 4096
#define D_DIM 1024
#define N_DIM 128
#define M_TOTAL (B_DIM * L_DIM)   // 32768
#define CHUNK 128
#define NCHUNK (L_DIM / CHUNK)    // 32
#define TOT_CHUNKS (B_DIM * NCHUNK) // 256

// Scratch (no cudaMalloc allowed)
__device__ float g_hsloc[(size_t)M_TOTAL * N_DIM];    // local scans, fp32
__device__ float g_carry[TOT_CHUNKS * N_DIM];
__device__ float g_prefix[TOT_CHUNKS * N_DIM];
__device__ float g_Apow[CHUNK * N_DIM];               // A^(i+1)
__device__ __nv_bfloat16 g_hsh[(size_t)M_TOTAL * N_DIM];
__device__ __nv_bfloat16 g_hsl[(size_t)M_TOTAL * N_DIM];
__device__ __nv_bfloat16 g_Bwh[N_DIM * D_DIM];
__device__ __nv_bfloat16 g_Bwl[N_DIM * D_DIM];
__device__ __nv_bfloat16 g_Cwh[D_DIM * N_DIM];
__device__ __nv_bfloat16 g_Cwl[D_DIM * N_DIM];

typedef unsigned long long u64;
typedef uint32_t u32;

__device__ __forceinline__ u32 smem_to_u32(const void* p) {
    u32 a;
    asm("{ .reg .u64 t; cvta.to.shared.u64 t, %1; cvt.u32.u64 %0, t; }"
        : "=r"(a) : "l"(p));
    return a;
}
__device__ __forceinline__ u32 swz(u32 o) { return o ^ ((o >> 3) & 0x70); }

__device__ __forceinline__ void ldsm4(u32* r, u32 addr) {
    asm volatile("ldmatrix.sync.aligned.m8n8.x4.shared.b16 {%0,%1,%2,%3}, [%4];"
                 : "=r"(r[0]), "=r"(r[1]), "=r"(r[2]), "=r"(r[3]) : "r"(addr));
}
__device__ __forceinline__ void mma16816(float* c, const u32* a, const u32* b) {
    asm volatile("mma.sync.aligned.m16n8k16.row.col.f32.bf16.bf16.f32 "
                 "{%0,%1,%2,%3}, {%4,%5,%6,%7}, {%8,%9}, {%0,%1,%2,%3};"
                 : "+f"(c[0]), "+f"(c[1]), "+f"(c[2]), "+f"(c[3])
                 : "r"(a[0]), "r"(a[1]), "r"(a[2]), "r"(a[3]),
                   "r"(b[0]), "r"(b[1]));
}
__device__ __forceinline__ u64 pack_bf16x4(float a, float b, float c, float d) {
    __nv_bfloat162 p0 = __floats2bfloat162_rn(a, b);
    __nv_bfloat162 p1 = __floats2bfloat162_rn(c, d);
    u32 lo = *(u32*)&p0, hi = *(u32*)&p1;
    return ((u64)hi << 32) | lo;
}
#define CP_ASYNC16(dst, src) \
    asm volatile("cp.async.cg.shared.global [%0], [%1], 16;" :: "r"(dst), "l"(src))
#define CP_COMMIT() asm volatile("cp.async.commit_group;")
#define CP_WAIT0() asm volatile("cp.async.wait_group 0;")
#define CP_WAIT1() asm volatile("cp.async.wait_group 1;")

// ───────── GEMM1: hs_local/carry = scan_local(x @ B_w^T) ─────────
// Mainloop identical to the 243.8µs baseline. Epilogue: acc -> smem (stride 132,
// conflict-free) -> per-column local scan -> hs_local fp32 + carry.
__global__ void __launch_bounds__(256)
gemm1_hmma(const float* __restrict__ A,
           const __nv_bfloat16* __restrict__ Bwh, const __nv_bfloat16* __restrict__ Bwl,
           float* __restrict__ hsloc, float* __restrict__ carry,
           const float* __restrict__ log_A)
{
    constexpr int KTOT = D_DIM;
    constexpr int KC = 32;
    constexpr int NC = KTOT / KC;      // 32
    constexpr int STAGE = 32768;       // A 16KB + B 16KB

    extern __shared__ char dsm[];
    const u32 raw = smem_to_u32(dsm);
    const u32 base = (raw + 1023u) & ~1023u;
    char* dbase = dsm + (base - raw);

    const int tid  = threadIdx.x;
    const int lane = tid & 31;
    const int warp = tid >> 5;
    const int wr = warp & 1;
    const int wc = warp >> 1;
    const long row0 = (long)blockIdx.y * 128;

    const int r   = tid >> 1;
    const int hv  = tid & 1;
    const int cf0 = hv * 16;
    const float* Arow = A + (row0 + r) * (long)KTOT;
    const __nv_bfloat16* Bsrc = (hv ? Bwl : Bwh) + (size_t)r * KTOT;

    const int g  = lane >> 3;
    const int ln = lane & 7;
    const int rA = wr * 64 + (g & 1) * 8 + ln;
    const int cA = (g >> 1) * 16;
    const int rB = wc * 32 + (g >> 1) * 8 + ln;
    const int cB = (g & 1) * 16;

    float acc[4][4][4];
#pragma unroll
    for (int i = 0; i < 4; i++)
#pragma unroll
        for (int j = 0; j < 4; j++)
#pragma unroll
            for (int q = 0; q < 4; q++) acc[i][j][q] = 0.0f;

    // prologue: prefetch A fp32 chunk0; issue B chunk0
    float4 pa[4];
#pragma unroll
    for (int q = 0; q < 4; q++) pa[q] = *(const float4*)(Arow + cf0 + q * 4);
    {
        const u32 bdst = base + 16384;
#pragma unroll
        for (int i = 0; i < 4; i++)
            CP_ASYNC16(bdst + swz((u32)r * 128 + hv * 64 + i * 16), Bsrc + i * 8);
        CP_COMMIT();
    }

    for (int c = 0; c < NC; c++) {
        const int s = c & 1;
        char* bufA = dbase + s * STAGE;

#pragma unroll
        for (int q = 0; q < 4; q++) {
            float4 v = pa[q];
            float hx = __bfloat162float(__float2bfloat16(v.x));
            float hy = __bfloat162float(__float2bfloat16(v.y));
            float hz = __bfloat162float(__float2bfloat16(v.z));
            float hw = __bfloat162float(__float2bfloat16(v.w));
            const u32 cbyte = (u32)(cf0 + q * 4) * 2;
            *(u64*)(bufA + swz((u32)r * 128 + cbyte))      = pack_bf16x4(hx, hy, hz, hw);
            *(u64*)(bufA + swz((u32)r * 128 + 64 + cbyte)) =
                pack_bf16x4(v.x - hx, v.y - hy, v.z - hz, v.w - hw);
        }
        if (c + 1 < NC) {
            const u32 bdst = base + ((c + 1) & 1) * STAGE + 16384;
            const __nv_bfloat16* src = Bsrc + (c + 1) * KC;
#pragma unroll
            for (int i = 0; i < 4; i++)
                CP_ASYNC16(bdst + swz((u32)r * 128 + hv * 64 + i * 16), src + i * 8);
            CP_COMMIT();
            CP_WAIT1();
        } else {
            CP_WAIT0();
        }
        __syncthreads();

        if (c + 1 < NC) {
            const int kn = (c + 1) * KC;
#pragma unroll
            for (int q = 0; q < 4; q++)
                pa[q] = *(const float4*)(Arow + kn + cf0 + q * 4);
        }

        const u32 ab = base + s * STAGE;
        const u32 bb = ab + 16384;
#pragma unroll
        for (int ks = 0; ks < 2; ks++) {
            const u32 kA = (u32)(ks * 32 + cA);
            const u32 kB = (u32)(ks * 32 + cB);
            u32 ah[4][4], al[4][4], bf[2][4];
#pragma unroll
            for (int mt = 0; mt < 4; mt++)
                ldsm4(ah[mt], ab + swz((u32)(rA + mt * 16) * 128 + kA));
#pragma unroll
            for (int p = 0; p < 2; p++)
                ldsm4(bf[p], bb + swz((u32)(rB + p * 16) * 128 + kB));
#pragma unroll
            for (int mt = 0; mt < 4; mt++)
#pragma unroll
                for (int nt = 0; nt < 4; nt++)
                    mma16816(acc[mt][nt], ah[mt], &bf[nt >> 1][(nt & 1) * 2]);
#pragma unroll
            for (int mt = 0; mt < 4; mt++)
                ldsm4(al[mt], ab + swz((u32)(rA + mt * 16) * 128 + 64 + kA));
#pragma unroll
            for (int mt = 0; mt < 4; mt++)
#pragma unroll
                for (int nt = 0; nt < 4; nt++)
                    mma16816(acc[mt][nt], al[mt], &bf[nt >> 1][(nt & 1) * 2]);
#pragma unroll
            for (int p = 0; p < 2; p++)
                ldsm4(bf[p], bb + swz((u32)(rB + p * 16) * 128 + 64 + kB));
#pragma unroll
            for (int mt = 0; mt < 4; mt++)
#pragma unroll
                for (int nt = 0; nt < 4; nt++)
                    mma16816(acc[mt][nt], ah[mt], &bf[nt >> 1][(nt & 1) * 2]);
        }
        __syncthreads();
    }

    // ── fused epilogue: acc -> smem (stride 132 floats) -> column scan ──
    float* sc = (float*)dbase;     // 128 x 132 floats = 67584 B, pipeline done
    const int er = lane >> 2;
    const int ec = (lane & 3) * 2;
#pragma unroll
    for (int mt = 0; mt < 4; mt++)
#pragma unroll
        for (int nt = 0; nt < 4; nt++) {
            const int m0 = wr * 64 + mt * 16 + er;
            const int n  = wc * 32 + nt * 8 + ec;
            *(float2*)(sc + m0 * 132 + n)       = make_float2(acc[mt][nt][0], acc[mt][nt][1]);
            *(float2*)(sc + (m0 + 8) * 132 + n) = make_float2(acc[mt][nt][2], acc[mt][nt][3]);
        }
    __syncthreads();

    if (tid < 128) {
        const int n = tid;
        const float Aa = expf(log_A[n]);
        float h = 0.0f;
        float* dst = hsloc + row0 * N_DIM + n;
#pragma unroll 8
        for (int l = 0; l < 128; l++) {
            h = fmaf(Aa, h, sc[l * 132 + n]);
            dst[(size_t)l * N_DIM] = h;
        }
        carry[blockIdx.y * N_DIM + n] = h;
    }
}

// ───────── GEMM2: y = hs @ C_w^T + x*Dp (unchanged from 243.8 baseline) ─────────
__global__ void __launch_bounds__(256, 2)
gemm2_hmma(const __nv_bfloat16* __restrict__ hsh, const __nv_bfloat16* __restrict__ hsl,
           const __nv_bfloat16* __restrict__ Cwh, const __nv_bfloat16* __restrict__ Cwl,
           float* __restrict__ C,
           const float* __restrict__ X, const float* __restrict__ Dp)
{
    constexpr int NVC = 6;
    constexpr int STAGE = 32768;

    extern __shared__ char dsm[];
    const u32 raw = smem_to_u32(dsm);
    const u32 base = (raw + 1023u) & ~1023u;

    const int tid  = threadIdx.x;
    const int lane = tid & 31;
    const int warp = tid >> 5;
    const int wr = warp & 1;
    const int wc = warp >> 1;
    const long row0 = (long)blockIdx.y * 128;
    const long col0 = (long)blockIdx.x * 128;

    const int r2 = tid >> 1;
    const int hv = tid & 1;

    const int g  = lane >> 3;
    const int ln = lane & 7;
    const int rA = wr * 64 + (g & 1) * 8 + ln;
    const int cA = (g >> 1) * 16;
    const int rB = wc * 32 + (g >> 1) * 8 + ln;
    const int cB = (g & 1) * 16;

    float acc[4][4][4];
#pragma unroll
    for (int i = 0; i < 4; i++)
#pragma unroll
        for (int j = 0; j < 4; j++)
#pragma unroll
            for (int q = 0; q < 4; q++) acc[i][j][q] = 0.0f;

    auto issue = [&](int vc) {
        const u32 sb = base + (vc % 3) * STAGE;
        const int t  = vc >> 1;
        const int kk = (vc & 1) * 64;
        const __nv_bfloat16* As = (t == 1) ? hsl : hsh;
        const __nv_bfloat16* Bs = (t == 2) ? Cwl : Cwh;
        const __nv_bfloat16* asrc = As + (row0 + r2) * (long)N_DIM + kk + hv * 32;
        const __nv_bfloat16* bsrc = Bs + (col0 + r2) * (long)N_DIM + kk + hv * 32;
#pragma unroll
        for (int i = 0; i < 4; i++)
            CP_ASYNC16(sb + swz((u32)r2 * 128 + hv * 64 + i * 16), asrc + i * 8);
#pragma unroll
        for (int i = 0; i < 4; i++)
            CP_ASYNC16(sb + 16384 + swz((u32)r2 * 128 + hv * 64 + i * 16), bsrc + i * 8);
        CP_COMMIT();
    };

    issue(0);
    issue(1);

    for (int vc = 0; vc < NVC; vc++) {
        if (vc + 1 < NVC) { CP_WAIT1(); } else { CP_WAIT0(); }
        __syncthreads();
        if (vc + 2 < NVC) issue(vc + 2);

        const u32 ab = base + (vc % 3) * STAGE;
        const u32 bb = ab + 16384;
#pragma unroll
        for (int ks = 0; ks < 4; ks++) {
            const u32 kA = (u32)(ks * 32 + cA);
            const u32 kB = (u32)(ks * 32 + cB);
            u32 ah[4][4], bf[2][4];
#pragma unroll
            for (int mt = 0; mt < 4; mt++)
                ldsm4(ah[mt], ab + swz((u32)(rA + mt * 16) * 128 + kA));
#pragma unroll
            for (int p = 0; p < 2; p++)
                ldsm4(bf[p], bb + swz((u32)(rB + p * 16) * 128 + kB));
#pragma unroll
            for (int mt = 0; mt < 4; mt++)
#pragma unroll
                for (int nt = 0; nt < 4; nt++)
                    mma16816(acc[mt][nt], ah[mt], &bf[nt >> 1][(nt & 1) * 2]);
        }
        __syncthreads();
    }

    const int er = lane >> 2;
    const int ec = (lane & 3) * 2;
#pragma unroll
    for (int mt = 0; mt < 4; mt++)
#pragma unroll
        for (int nt = 0; nt < 4; nt++) {
            const long m = row0 + wr * 64 + mt * 16 + er;
            const long n = col0 + wc * 32 + nt * 8 + ec;
            float2 dv = *(const float2*)(Dp + n);
            float2 x0 = *(const float2*)(X + m * (long)D_DIM + n);
            float2 x1 = *(const float2*)(X + (m + 8) * (long)D_DIM + n);
            float2 o0, o1;
            o0.x = fmaf(x0.x, dv.x, acc[mt][nt][0]);
            o0.y = fmaf(x0.y, dv.y, acc[mt][nt][1]);
            o1.x = fmaf(x1.x, dv.x, acc[mt][nt][2]);
            o1.y = fmaf(x1.y, dv.y, acc[mt][nt][3]);
            *(float2*)(C + m * (long)D_DIM + n) = o0;
            *(float2*)(C + (m + 8) * (long)D_DIM + n) = o1;
        }
}

// ───────── fused weight presplit ─────────
__global__ void split_both_kernel(const float* __restrict__ Bw, const float* __restrict__ Cw,
                                  __nv_bfloat16* __restrict__ Bwh, __nv_bfloat16* __restrict__ Bwl,
                                  __nv_bfloat16* __restrict__ Cwh, __nv_bfloat16* __restrict__ Cwl)
{
    const int nb = N_DIM * D_DIM;
    int i = blockIdx.x * blockDim.x + threadIdx.x;
    const float* src;
    __nv_bfloat16 *dh, *dl;
    int j;
    if (i < nb) { src = Bw; dh = Bwh; dl = Bwl; j = i; }
    else        { src = Cw; dh = Cwh; dl = Cwl; j = i - nb; if (j >= D_DIM * N_DIM) return; }
    float v = src[j];
    __nv_bfloat16 h = __float2bfloat16(v);
    dh[j] = h;
    dl[j] = __float2bfloat16(v - __bfloat162float(h));
}

// ───────── carry scan (exclusive prefix across 32 chunks) + Apow + final_state ─────
__global__ void __launch_bounds__(128)
carry_scan(const float* __restrict__ carry, float* __restrict__ prefix,
           const float* __restrict__ log_A, float* __restrict__ Apow,
           const float* __restrict__ hsloc, float* __restrict__ fs)
{
    int n = threadIdx.x;
    int b = blockIdx.x;
    float Aa = expf(log_A[n]);
    if (b == 0) {
        float pw = Aa;
#pragma unroll 8
        for (int i = 0; i < CHUNK; i++) {
            Apow[(size_t)i * N_DIM + n] = pw;   // A^(i+1)
            pw *= Aa;
        }
    }
    float Ac = expf((float)CHUNK * log_A[n]);
    float h = 0.0f;
#pragma unroll
    for (int c = 0; c < NCHUNK; c++) {
        prefix[(b * NCHUNK + c) * N_DIM + n] = h;   // exclusive
        h = fmaf(Ac, h, carry[(b * NCHUNK + c) * N_DIM + n]);
    }
    // final_state: u_{L-1} = h_{L-1} - A*h_{L-2} (local within last chunk)
    float s = 0.0f;
#pragma unroll
    for (int bb = 0; bb < B_DIM; bb++) {
        float hL1 = hsloc[((size_t)bb * L_DIM + (L_DIM - 1)) * N_DIM + n];
        float hL2 = hsloc[((size_t)bb * L_DIM + (L_DIM - 2)) * N_DIM + n];
        s += hL1 - Aa * hL2;
    }
    fs[b * N_DIM + n] = s * (1.0f / B_DIM);
}

// ───────── fix + split: hs = hs_local + Apow*prefix -> bf16 hi/lo (elementwise) ─────
__global__ void __launch_bounds__(256)
fix_split(const float* __restrict__ hsloc, const float* __restrict__ prefix,
          const float* __restrict__ Apow,
          __nv_bfloat16* __restrict__ hsh, __nv_bfloat16* __restrict__ hsl)
{
    size_t i = ((size_t)blockIdx.x * 256 + threadIdx.x) * 4;
    const int m  = (int)(i >> 7);
    const int n0 = (int)(i & 127);
    float4 v  = *(const float4*)(hsloc + i);
    float4 ap = *(const float4*)(Apow + ((size_t)(m & 127) << 7) + n0);
    float4 pf = *(const float4*)(prefix + ((size_t)(m >> 7) << 7) + n0);
    float hx = fmaf(ap.x, pf.x, v.x);
    float hy = fmaf(ap.y, pf.y, v.y);
    float hz = fmaf(ap.z, pf.z, v.z);
    float hw = fmaf(ap.w, pf.w, v.w);
    float bx = __bfloat162float(__float2bfloat16(hx));
    float by = __bfloat162float(__float2bfloat16(hy));
    float bz = __bfloat162float(__float2bfloat16(hz));
    float bw = __bfloat162float(__float2bfloat16(hw));
    *(u64*)(hsh + i) = pack_bf16x4(bx, by, bz, bw);
    *(u64*)(hsl + i) = pack_bf16x4(hx - bx, hy - by, hz - bz, hw - bw);
}

// ─────────────────────────────── launch ───────────────────────────────
extern "C" void kernel_launch(void* const* d_in, const int* in_sizes, int n_in,
                              void* d_out, int out_size)
{
    const float* x       = (const float*)d_in[0];
    const float* B_w     = (const float*)d_in[1];
    const float* C_w     = (const float*)d_in[2];
    const float* log_A   = (const float*)d_in[3];
    const float* D_param = (const float*)d_in[4];

    float* y  = (float*)d_out;
    float* fs = y + ((size_t)out_size - (size_t)B_DIM * N_DIM);

    float *hsloc, *carry, *prefix, *Apow;
    __nv_bfloat16 *hsh, *hsl, *Bwh, *Bwl, *Cwh, *Cwl;
    cudaGetSymbolAddress((void**)&hsloc, g_hsloc);
    cudaGetSymbolAddress((void**)&carry, g_carry);
    cudaGetSymbolAddress((void**)&prefix, g_prefix);
    cudaGetSymbolAddress((void**)&Apow, g_Apow);
    cudaGetSymbolAddress((void**)&hsh, g_hsh);
    cudaGetSymbolAddress((void**)&hsl, g_hsl);
    cudaGetSymbolAddress((void**)&Bwh, g_Bwh);
    cudaGetSymbolAddress((void**)&Bwl, g_Bwl);
    cudaGetSymbolAddress((void**)&Cwh, g_Cwh);
    cudaGetSymbolAddress((void**)&Cwl, g_Cwl);

    const int SMEM1 = 128 * 132 * 4 + 1024;   // 68608 (epilogue scan buffer)
    const int SMEM2 = 3 * 32768 + 1024;       // 99328
    cudaFuncSetAttribute(gemm1_hmma, cudaFuncAttributeMaxDynamicSharedMemorySize, SMEM1);
    cudaFuncSetAttribute(gemm2_hmma, cudaFuncAttributeMaxDynamicSharedMemorySize, SMEM2);

    split_both_kernel<<<(2 * N_DIM * D_DIM + 255) / 256, 256>>>(B_w, C_w, Bwh, Bwl, Cwh, Cwl);

    // GEMM1 + fused local scan
    {
        dim3 grid(1, M_TOTAL / 128);
        gemm1_hmma<<<grid, 256, SMEM1>>>(x, Bwh, Bwl, hsloc, carry, log_A);
    }

    // carry prefix (+Apow, +final_state)
    carry_scan<<<B_DIM, 128>>>(carry, prefix, log_A, Apow, hsloc, fs);

    // elementwise fix + bf16 split
    fix_split<<<(int)(((size_t)M_TOTAL * N_DIM / 4) / 256), 256>>>(hsloc, prefix, Apow, hsh, hsl);

    // GEMM2: y = hs @ C_w^T + x * D_param
    {
        dim3 grid(D_DIM / 128, M_TOTAL / 128);
        gemm2_hmma<<<grid, 256, SMEM2>>>(hsh, hsl, Cwh, Cwl, y, x, D_param);
    }
}

// round 15
// speedup vs baseline: 1.2241x; 1.0812x over previous
#include <cuda_runtime.h>
#include <cuda_bf16.h>
#include <cuda_fp16.h>
#include <cstdint>

#define B_DIM 8
#define L_DIM 4096
#define D_DIM 1024
#define N_DIM 128
#define M_TOTAL (B_DIM * L_DIM)   // 32768
#define CHUNK 128
#define NCHUNK (L_DIM / CHUNK)    // 32
#define TOT_CHUNKS (B_DIM * NCHUNK) // 256

#define BW_SCALE 256.0f
#define BW_DESCALE (1.0f / 256.0f)

// Scratch (no cudaMalloc allowed)
__device__ float g_hsloc[(size_t)M_TOTAL * N_DIM];    // local scans, fp32
__device__ float g_carry[TOT_CHUNKS * N_DIM];
__device__ float g_prefix[TOT_CHUNKS * N_DIM];
__device__ float g_Apow[CHUNK * N_DIM];               // A^(i+1)
__device__ __nv_bfloat16 g_hsh[(size_t)M_TOTAL * N_DIM];
__device__ __nv_bfloat16 g_hsl[(size_t)M_TOTAL * N_DIM];
__device__ __half g_Bwh[N_DIM * D_DIM];               // fp16, x256 scaled
__device__ __half g_Bwl[N_DIM * D_DIM];
__device__ __nv_bfloat16 g_Cwh[D_DIM * N_DIM];
__device__ __nv_bfloat16 g_Cwl[D_DIM * N_DIM];

typedef unsigned long long u64;
typedef uint32_t u32;

__device__ __forceinline__ u32 smem_to_u32(const void* p) {
    u32 a;
    asm("{ .reg .u64 t; cvta.to.shared.u64 t, %1; cvt.u32.u64 %0, t; }"
        : "=r"(a) : "l"(p));
    return a;
}
__device__ __forceinline__ u32 swz(u32 o) { return o ^ ((o >> 3) & 0x70); }

__device__ __forceinline__ void ldsm4(u32* r, u32 addr) {
    asm volatile("ldmatrix.sync.aligned.m8n8.x4.shared.b16 {%0,%1,%2,%3}, [%4];"
                 : "=r"(r[0]), "=r"(r[1]), "=r"(r[2]), "=r"(r[3]) : "r"(addr));
}
__device__ __forceinline__ void mma_bf16(float* c, const u32* a, const u32* b) {
    asm volatile("mma.sync.aligned.m16n8k16.row.col.f32.bf16.bf16.f32 "
                 "{%0,%1,%2,%3}, {%4,%5,%6,%7}, {%8,%9}, {%0,%1,%2,%3};"
                 : "+f"(c[0]), "+f"(c[1]), "+f"(c[2]), "+f"(c[3])
                 : "r"(a[0]), "r"(a[1]), "r"(a[2]), "r"(a[3]),
                   "r"(b[0]), "r"(b[1]));
}
__device__ __forceinline__ void mma_f16(float* c, const u32* a, const u32* b) {
    asm volatile("mma.sync.aligned.m16n8k16.row.col.f32.f16.f16.f32 "
                 "{%0,%1,%2,%3}, {%4,%5,%6,%7}, {%8,%9}, {%0,%1,%2,%3};"
                 : "+f"(c[0]), "+f"(c[1]), "+f"(c[2]), "+f"(c[3])
                 : "r"(a[0]), "r"(a[1]), "r"(a[2]), "r"(a[3]),
                   "r"(b[0]), "r"(b[1]));
}
__device__ __forceinline__ u64 pack_bf16x4(float a, float b, float c, float d) {
    __nv_bfloat162 p0 = __floats2bfloat162_rn(a, b);
    __nv_bfloat162 p1 = __floats2bfloat162_rn(c, d);
    u32 lo = *(u32*)&p0, hi = *(u32*)&p1;
    return ((u64)hi << 32) | lo;
}
__device__ __forceinline__ u64 pack_f16x4(float a, float b, float c, float d) {
    __half2 p0 = __floats2half2_rn(a, b);
    __half2 p1 = __floats2half2_rn(c, d);
    u32 lo = *(u32*)&p0, hi = *(u32*)&p1;
    return ((u64)hi << 32) | lo;
}
#define CP_ASYNC16(dst, src) \
    asm volatile("cp.async.cg.shared.global [%0], [%1], 16;" :: "r"(dst), "l"(src))
#define CP_COMMIT() asm volatile("cp.async.commit_group;")
#define CP_WAIT0() asm volatile("cp.async.wait_group 0;")
#define CP_WAIT1() asm volatile("cp.async.wait_group 1;")

// ───────── GEMM1 (fp16 2-chain): hs_local/carry = scan_local((x @ B_w^T)/256) ─────
// A (x) converted to single fp16; B presplit fp16 (x256), chains AhBh + AhBl.
// Structure otherwise identical to the 237.4µs baseline (no minBlocks cap).
__global__ void __launch_bounds__(256)
gemm1_hmma(const float* __restrict__ A,
           const __half* __restrict__ Bwh, const __half* __restrict__ Bwl,
           float* __restrict__ hsloc, float* __restrict__ carry,
           const float* __restrict__ log_A)
{
    constexpr int KTOT = D_DIM;
    constexpr int KC = 32;
    constexpr int NC = KTOT / KC;      // 32
    constexpr int STAGE = 32768;       // A 16KB (half used) + B 16KB

    extern __shared__ char dsm[];
    const u32 raw = smem_to_u32(dsm);
    const u32 base = (raw + 1023u) & ~1023u;
    char* dbase = dsm + (base - raw);

    const int tid  = threadIdx.x;
    const int lane = tid & 31;
    const int warp = tid >> 5;
    const int wr = warp & 1;
    const int wc = warp >> 1;
    const long row0 = (long)blockIdx.y * 128;

    const int r   = tid >> 1;
    const int hv  = tid & 1;
    const int cf0 = hv * 16;
    const float* Arow = A + (row0 + r) * (long)KTOT;
    const __half* Bsrc = (hv ? Bwl : Bwh) + (size_t)r * KTOT;

    const int g  = lane >> 3;
    const int ln = lane & 7;
    const int rA = wr * 64 + (g & 1) * 8 + ln;
    const int cA = (g >> 1) * 16;
    const int rB = wc * 32 + (g >> 1) * 8 + ln;
    const int cB = (g & 1) * 16;

    float acc[4][4][4];
#pragma unroll
    for (int i = 0; i < 4; i++)
#pragma unroll
        for (int j = 0; j < 4; j++)
#pragma unroll
            for (int q = 0; q < 4; q++) acc[i][j][q] = 0.0f;

    // prologue: prefetch A fp32 chunk0; issue B chunk0
    float4 pa[4];
#pragma unroll
    for (int q = 0; q < 4; q++) pa[q] = *(const float4*)(Arow + cf0 + q * 4);
    {
        const u32 bdst = base + 16384;
#pragma unroll
        for (int i = 0; i < 4; i++)
            CP_ASYNC16(bdst + swz((u32)r * 128 + hv * 64 + i * 16), Bsrc + i * 8);
        CP_COMMIT();
    }

    for (int c = 0; c < NC; c++) {
        const int s = c & 1;
        char* bufA = dbase + s * STAGE;

        // convert A chunk c: single fp16 (4 stores, no residual math)
#pragma unroll
        for (int q = 0; q < 4; q++) {
            float4 v = pa[q];
            const u32 cbyte = (u32)(cf0 + q * 4) * 2;
            *(u64*)(bufA + swz((u32)r * 128 + cbyte)) =
                pack_f16x4(v.x, v.y, v.z, v.w);
        }
        if (c + 1 < NC) {
            const u32 bdst = base + ((c + 1) & 1) * STAGE + 16384;
            const __half* src = Bsrc + (c + 1) * KC;
#pragma unroll
            for (int i = 0; i < 4; i++)
                CP_ASYNC16(bdst + swz((u32)r * 128 + hv * 64 + i * 16), src + i * 8);
            CP_COMMIT();
            CP_WAIT1();
        } else {
            CP_WAIT0();
        }
        __syncthreads();

        if (c + 1 < NC) {
            const int kn = (c + 1) * KC;
#pragma unroll
            for (int q = 0; q < 4; q++)
                pa[q] = *(const float4*)(Arow + kn + cf0 + q * 4);
        }

        const u32 ab = base + s * STAGE;
        const u32 bb = ab + 16384;
#pragma unroll
        for (int ks = 0; ks < 2; ks++) {
            const u32 kA = (u32)(ks * 32 + cA);
            const u32 kB = (u32)(ks * 32 + cB);
            u32 ah[4][4], bf[2][4];
#pragma unroll
            for (int mt = 0; mt < 4; mt++)
                ldsm4(ah[mt], ab + swz((u32)(rA + mt * 16) * 128 + kA));
            // Bh chain
#pragma unroll
            for (int p = 0; p < 2; p++)
                ldsm4(bf[p], bb + swz((u32)(rB + p * 16) * 128 + kB));
#pragma unroll
            for (int mt = 0; mt < 4; mt++)
#pragma unroll
                for (int nt = 0; nt < 4; nt++)
                    mma_f16(acc[mt][nt], ah[mt], &bf[nt >> 1][(nt & 1) * 2]);
            // Bl chain
#pragma unroll
            for (int p = 0; p < 2; p++)
                ldsm4(bf[p], bb + swz((u32)(rB + p * 16) * 128 + 64 + kB));
#pragma unroll
            for (int mt = 0; mt < 4; mt++)
#pragma unroll
                for (int nt = 0; nt < 4; nt++)
                    mma_f16(acc[mt][nt], ah[mt], &bf[nt >> 1][(nt & 1) * 2]);
        }
        __syncthreads();
    }

    // ── fused epilogue: acc/256 -> smem (stride 132) -> column scan ──
    float* sc = (float*)dbase;
    const int er = lane >> 2;
    const int ec = (lane & 3) * 2;
#pragma unroll
    for (int mt = 0; mt < 4; mt++)
#pragma unroll
        for (int nt = 0; nt < 4; nt++) {
            const int m0 = wr * 64 + mt * 16 + er;
            const int n  = wc * 32 + nt * 8 + ec;
            *(float2*)(sc + m0 * 132 + n) =
                make_float2(acc[mt][nt][0] * BW_DESCALE, acc[mt][nt][1] * BW_DESCALE);
            *(float2*)(sc + (m0 + 8) * 132 + n) =
                make_float2(acc[mt][nt][2] * BW_DESCALE, acc[mt][nt][3] * BW_DESCALE);
        }
    __syncthreads();

    if (tid < 128) {
        const int n = tid;
        const float Aa = expf(log_A[n]);
        float h = 0.0f;
        float* dst = hsloc + row0 * N_DIM + n;
#pragma unroll 8
        for (int l = 0; l < 128; l++) {
            h = fmaf(Aa, h, sc[l * 132 + n]);
            dst[(size_t)l * N_DIM] = h;
        }
        carry[blockIdx.y * N_DIM + n] = h;
    }
}

// ───────── GEMM2: y = hs @ C_w^T + x*Dp (unchanged bf16 3-chain) ─────────
__global__ void __launch_bounds__(256, 2)
gemm2_hmma(const __nv_bfloat16* __restrict__ hsh, const __nv_bfloat16* __restrict__ hsl,
           const __nv_bfloat16* __restrict__ Cwh, const __nv_bfloat16* __restrict__ Cwl,
           float* __restrict__ C,
           const float* __restrict__ X, const float* __restrict__ Dp)
{
    constexpr int NVC = 6;
    constexpr int STAGE = 32768;

    extern __shared__ char dsm[];
    const u32 raw = smem_to_u32(dsm);
    const u32 base = (raw + 1023u) & ~1023u;

    const int tid  = threadIdx.x;
    const int lane = tid & 31;
    const int warp = tid >> 5;
    const int wr = warp & 1;
    const int wc = warp >> 1;
    const long row0 = (long)blockIdx.y * 128;
    const long col0 = (long)blockIdx.x * 128;

    const int r2 = tid >> 1;
    const int hv = tid & 1;

    const int g  = lane >> 3;
    const int ln = lane & 7;
    const int rA = wr * 64 + (g & 1) * 8 + ln;
    const int cA = (g >> 1) * 16;
    const int rB = wc * 32 + (g >> 1) * 8 + ln;
    const int cB = (g & 1) * 16;

    float acc[4][4][4];
#pragma unroll
    for (int i = 0; i < 4; i++)
#pragma unroll
        for (int j = 0; j < 4; j++)
#pragma unroll
            for (int q = 0; q < 4; q++) acc[i][j][q] = 0.0f;

    auto issue = [&](int vc) {
        const u32 sb = base + (vc % 3) * STAGE;
        const int t  = vc >> 1;
        const int kk = (vc & 1) * 64;
        const __nv_bfloat16* As = (t == 1) ? hsl : hsh;
        const __nv_bfloat16* Bs = (t == 2) ? Cwl : Cwh;
        const __nv_bfloat16* asrc = As + (row0 + r2) * (long)N_DIM + kk + hv * 32;
        const __nv_bfloat16* bsrc = Bs + (col0 + r2) * (long)N_DIM + kk + hv * 32;
#pragma unroll
        for (int i = 0; i < 4; i++)
            CP_ASYNC16(sb + swz((u32)r2 * 128 + hv * 64 + i * 16), asrc + i * 8);
#pragma unroll
        for (int i = 0; i < 4; i++)
            CP_ASYNC16(sb + 16384 + swz((u32)r2 * 128 + hv * 64 + i * 16), bsrc + i * 8);
        CP_COMMIT();
    };

    issue(0);
    issue(1);

    for (int vc = 0; vc < NVC; vc++) {
        if (vc + 1 < NVC) { CP_WAIT1(); } else { CP_WAIT0(); }
        __syncthreads();
        if (vc + 2 < NVC) issue(vc + 2);

        const u32 ab = base + (vc % 3) * STAGE;
        const u32 bb = ab + 16384;
#pragma unroll
        for (int ks = 0; ks < 4; ks++) {
            const u32 kA = (u32)(ks * 32 + cA);
            const u32 kB = (u32)(ks * 32 + cB);
            u32 ah[4][4], bf[2][4];
#pragma unroll
            for (int mt = 0; mt < 4; mt++)
                ldsm4(ah[mt], ab + swz((u32)(rA + mt * 16) * 128 + kA));
#pragma unroll
            for (int p = 0; p < 2; p++)
                ldsm4(bf[p], bb + swz((u32)(rB + p * 16) * 128 + kB));
#pragma unroll
            for (int mt = 0; mt < 4; mt++)
#pragma unroll
                for (int nt = 0; nt < 4; nt++)
                    mma_bf16(acc[mt][nt], ah[mt], &bf[nt >> 1][(nt & 1) * 2]);
        }
        __syncthreads();
    }

    const int er = lane >> 2;
    const int ec = (lane & 3) * 2;
#pragma unroll
    for (int mt = 0; mt < 4; mt++)
#pragma unroll
        for (int nt = 0; nt < 4; nt++) {
            const long m = row0 + wr * 64 + mt * 16 + er;
            const long n = col0 + wc * 32 + nt * 8 + ec;
            float2 dv = *(const float2*)(Dp + n);
            float2 x0 = *(const float2*)(X + m * (long)D_DIM + n);
            float2 x1 = *(const float2*)(X + (m + 8) * (long)D_DIM + n);
            float2 o0, o1;
            o0.x = fmaf(x0.x, dv.x, acc[mt][nt][0]);
            o0.y = fmaf(x0.y, dv.y, acc[mt][nt][1]);
            o1.x = fmaf(x1.x, dv.x, acc[mt][nt][2]);
            o1.y = fmaf(x1.y, dv.y, acc[mt][nt][3]);
            *(float2*)(C + m * (long)D_DIM + n) = o0;
            *(float2*)(C + (m + 8) * (long)D_DIM + n) = o1;
        }
}

// ───────── fused weight presplit: B_w (fp16, x256) + C_w (bf16) ─────────
__global__ void split_both_kernel(const float* __restrict__ Bw, const float* __restrict__ Cw,
                                  __half* __restrict__ Bwh, __half* __restrict__ Bwl,
                                  __nv_bfloat16* __restrict__ Cwh, __nv_bfloat16* __restrict__ Cwl)
{
    const int nb = N_DIM * D_DIM;
    int i = blockIdx.x * blockDim.x + threadIdx.x;
    if (i < nb) {
        float v = Bw[i] * BW_SCALE;
        __half h = __float2half_rn(v);
        Bwh[i] = h;
        Bwl[i] = __float2half_rn(v - __half2float(h));
    } else {
        int j = i - nb;
        if (j >= D_DIM * N_DIM) return;
        float v = Cw[j];
        __nv_bfloat16 h = __float2bfloat16(v);
        Cwh[j] = h;
        Cwl[j] = __float2bfloat16(v - __bfloat162float(h));
    }
}

// ───────── carry scan + Apow + final_state (unchanged) ─────────
__global__ void __launch_bounds__(128)
carry_scan(const float* __restrict__ carry, float* __restrict__ prefix,
           const float* __restrict__ log_A, float* __restrict__ Apow,
           const float* __restrict__ hsloc, float* __restrict__ fs)
{
    int n = threadIdx.x;
    int b = blockIdx.x;
    float Aa = expf(log_A[n]);
    if (b == 0) {
        float pw = Aa;
#pragma unroll 8
        for (int i = 0; i < CHUNK; i++) {
            Apow[(size_t)i * N_DIM + n] = pw;   // A^(i+1)
            pw *= Aa;
        }
    }
    float Ac = expf((float)CHUNK * log_A[n]);
    float h = 0.0f;
#pragma unroll
    for (int c = 0; c < NCHUNK; c++) {
        prefix[(b * NCHUNK + c) * N_DIM + n] = h;   // exclusive
        h = fmaf(Ac, h, carry[(b * NCHUNK + c) * N_DIM + n]);
    }
    float s = 0.0f;
#pragma unroll
    for (int bb = 0; bb < B_DIM; bb++) {
        float hL1 = hsloc[((size_t)bb * L_DIM + (L_DIM - 1)) * N_DIM + n];
        float hL2 = hsloc[((size_t)bb * L_DIM + (L_DIM - 2)) * N_DIM + n];
        s += hL1 - Aa * hL2;
    }
    fs[b * N_DIM + n] = s * (1.0f / B_DIM);
}

// ───────── fix + split (unchanged) ─────────
__global__ void __launch_bounds__(256)
fix_split(const float* __restrict__ hsloc, const float* __restrict__ prefix,
          const float* __restrict__ Apow,
          __nv_bfloat16* __restrict__ hsh, __nv_bfloat16* __restrict__ hsl)
{
    size_t i = ((size_t)blockIdx.x * 256 + threadIdx.x) * 4;
    const int m  = (int)(i >> 7);
    const int n0 = (int)(i & 127);
    float4 v  = *(const float4*)(hsloc + i);
    float4 ap = *(const float4*)(Apow + ((size_t)(m & 127) << 7) + n0);
    float4 pf = *(const float4*)(prefix + ((size_t)(m >> 7) << 7) + n0);
    float hx = fmaf(ap.x, pf.x, v.x);
    float hy = fmaf(ap.y, pf.y, v.y);
    float hz = fmaf(ap.z, pf.z, v.z);
    float hw = fmaf(ap.w, pf.w, v.w);
    float bx = __bfloat162float(__float2bfloat16(hx));
    float by = __bfloat162float(__float2bfloat16(hy));
    float bz = __bfloat162float(__float2bfloat16(hz));
    float bw = __bfloat162float(__float2bfloat16(hw));
    *(u64*)(hsh + i) = pack_bf16x4(bx, by, bz, bw);
    *(u64*)(hsl + i) = pack_bf16x4(hx - bx, hy - by, hz - bz, hw - bw);
}

// ─────────────────────────────── launch ───────────────────────────────
extern "C" void kernel_launch(void* const* d_in, const int* in_sizes, int n_in,
                              void* d_out, int out_size)
{
    const float* x       = (const float*)d_in[0];
    const float* B_w     = (const float*)d_in[1];
    const float* C_w     = (const float*)d_in[2];
    const float* log_A   = (const float*)d_in[3];
    const float* D_param = (const float*)d_in[4];

    float* y  = (float*)d_out;
    float* fs = y + ((size_t)out_size - (size_t)B_DIM * N_DIM);

    float *hsloc, *carry, *prefix, *Apow;
    __nv_bfloat16 *hsh, *hsl, *Cwh, *Cwl;
    __half *Bwh, *Bwl;
    cudaGetSymbolAddress((void**)&hsloc, g_hsloc);
    cudaGetSymbolAddress((void**)&carry, g_carry);
    cudaGetSymbolAddress((void**)&prefix, g_prefix);
    cudaGetSymbolAddress((void**)&Apow, g_Apow);
    cudaGetSymbolAddress((void**)&hsh, g_hsh);
    cudaGetSymbolAddress((void**)&hsl, g_hsl);
    cudaGetSymbolAddress((void**)&Bwh, g_Bwh);
    cudaGetSymbolAddress((void**)&Bwl, g_Bwl);
    cudaGetSymbolAddress((void**)&Cwh, g_Cwh);
    cudaGetSymbolAddress((void**)&Cwl, g_Cwl);

    const int SMEM1 = 128 * 132 * 4 + 1024;   // 68608
    const int SMEM2 = 3 * 32768 + 1024;       // 99328
    cudaFuncSetAttribute(gemm1_hmma, cudaFuncAttributeMaxDynamicSharedMemorySize, SMEM1);
    cudaFuncSetAttribute(gemm2_hmma, cudaFuncAttributeMaxDynamicSharedMemorySize, SMEM2);

    split_both_kernel<<<(2 * N_DIM * D_DIM + 255) / 256, 256>>>(B_w, C_w, Bwh, Bwl, Cwh, Cwl);

    // GEMM1 (fp16 2-chain) + fused local scan
    {
        dim3 grid(1, M_TOTAL / 128);
        gemm1_hmma<<<grid, 256, SMEM1>>>(x, Bwh, Bwl, hsloc, carry, log_A);
    }

    // carry prefix (+Apow, +final_state)
    carry_scan<<<B_DIM, 128>>>(carry, prefix, log_A, Apow, hsloc, fs);

    // elementwise fix + bf16 split
    fix_split<<<(int)(((size_t)M_TOTAL * N_DIM / 4) / 256), 256>>>(hsloc, prefix, Apow, hsh, hsl);

    // GEMM2: y = hs @ C_w^T + x * D_param
    {
        dim3 grid(D_DIM / 128, M_TOTAL / 128);
        gemm2_hmma<<<grid, 256, SMEM2>>>(hsh, hsl, Cwh, Cwl, y, x, D_param);
    }
}

// round 16
// speedup vs baseline: 1.4184x; 1.1587x over previous
#include <cuda_runtime.h>
#include <cuda_bf16.h>
#include <cuda_fp16.h>
#include <cstdint>

#define B_DIM 8
#define L_DIM 4096
#define D_DIM 1024
#define N_DIM 128
#define M_TOTAL (B_DIM * L_DIM)   // 32768
#define CHUNK 128
#define NCHUNK (L_DIM / CHUNK)    // 32
#define TOT_CHUNKS (B_DIM * NCHUNK) // 256

#define W_SCALE 256.0f
#define W_DESCALE (1.0f / 256.0f)

// Scratch (no cudaMalloc allowed)
__device__ float g_hsloc[(size_t)M_TOTAL * N_DIM];    // local scans, fp32
__device__ float g_carry[TOT_CHUNKS * N_DIM];
__device__ float g_prefix[TOT_CHUNKS * N_DIM];
__device__ float g_Apow[CHUNK * N_DIM];               // A^(i+1)
__device__ __half g_hsf[(size_t)M_TOTAL * N_DIM];     // fixed hs, fp16
__device__ __half g_Bwh[N_DIM * D_DIM];               // fp16, x256 scaled
__device__ __half g_Bwl[N_DIM * D_DIM];
__device__ __half g_Cwh[D_DIM * N_DIM];               // fp16, x256 scaled
__device__ __half g_Cwl[D_DIM * N_DIM];

typedef unsigned long long u64;
typedef uint32_t u32;

__device__ __forceinline__ u32 smem_to_u32(const void* p) {
    u32 a;
    asm("{ .reg .u64 t; cvta.to.shared.u64 t, %1; cvt.u32.u64 %0, t; }"
        : "=r"(a) : "l"(p));
    return a;
}
__device__ __forceinline__ u32 swz(u32 o) { return o ^ ((o >> 3) & 0x70); }

__device__ __forceinline__ void ldsm4(u32* r, u32 addr) {
    asm volatile("ldmatrix.sync.aligned.m8n8.x4.shared.b16 {%0,%1,%2,%3}, [%4];"
                 : "=r"(r[0]), "=r"(r[1]), "=r"(r[2]), "=r"(r[3]) : "r"(addr));
}
__device__ __forceinline__ void mma_f16(float* c, const u32* a, const u32* b) {
    asm volatile("mma.sync.aligned.m16n8k16.row.col.f32.f16.f16.f32 "
                 "{%0,%1,%2,%3}, {%4,%5,%6,%7}, {%8,%9}, {%0,%1,%2,%3};"
                 : "+f"(c[0]), "+f"(c[1]), "+f"(c[2]), "+f"(c[3])
                 : "r"(a[0]), "r"(a[1]), "r"(a[2]), "r"(a[3]),
                   "r"(b[0]), "r"(b[1]));
}
__device__ __forceinline__ u64 pack_f16x4(float a, float b, float c, float d) {
    __half2 p0 = __floats2half2_rn(a, b);
    __half2 p1 = __floats2half2_rn(c, d);
    u32 lo = *(u32*)&p0, hi = *(u32*)&p1;
    return ((u64)hi << 32) | lo;
}
#define CP_ASYNC16(dst, src) \
    asm volatile("cp.async.cg.shared.global [%0], [%1], 16;" :: "r"(dst), "l"(src))
#define CP_COMMIT() asm volatile("cp.async.commit_group;")
#define CP_WAIT0() asm volatile("cp.async.wait_group 0;")
#define CP_WAIT1() asm volatile("cp.async.wait_group 1;")

// ───────── GEMM1 (fp16 2-chain): hs_local/carry = scan_local((x @ B_w^T)/256) ─────
// Unchanged from the 219.6µs baseline.
__global__ void __launch_bounds__(256)
gemm1_hmma(const float* __restrict__ A,
           const __half* __restrict__ Bwh, const __half* __restrict__ Bwl,
           float* __restrict__ hsloc, float* __restrict__ carry,
           const float* __restrict__ log_A)
{
    constexpr int KTOT = D_DIM;
    constexpr int KC = 32;
    constexpr int NC = KTOT / KC;      // 32
    constexpr int STAGE = 32768;

    extern __shared__ char dsm[];
    const u32 raw = smem_to_u32(dsm);
    const u32 base = (raw + 1023u) & ~1023u;
    char* dbase = dsm + (base - raw);

    const int tid  = threadIdx.x;
    const int lane = tid & 31;
    const int warp = tid >> 5;
    const int wr = warp & 1;
    const int wc = warp >> 1;
    const long row0 = (long)blockIdx.y * 128;

    const int r   = tid >> 1;
    const int hv  = tid & 1;
    const int cf0 = hv * 16;
    const float* Arow = A + (row0 + r) * (long)KTOT;
    const __half* Bsrc = (hv ? Bwl : Bwh) + (size_t)r * KTOT;

    const int g  = lane >> 3;
    const int ln = lane & 7;
    const int rA = wr * 64 + (g & 1) * 8 + ln;
    const int cA = (g >> 1) * 16;
    const int rB = wc * 32 + (g >> 1) * 8 + ln;
    const int cB = (g & 1) * 16;

    float acc[4][4][4];
#pragma unroll
    for (int i = 0; i < 4; i++)
#pragma unroll
        for (int j = 0; j < 4; j++)
#pragma unroll
            for (int q = 0; q < 4; q++) acc[i][j][q] = 0.0f;

    float4 pa[4];
#pragma unroll
    for (int q = 0; q < 4; q++) pa[q] = *(const float4*)(Arow + cf0 + q * 4);
    {
        const u32 bdst = base + 16384;
#pragma unroll
        for (int i = 0; i < 4; i++)
            CP_ASYNC16(bdst + swz((u32)r * 128 + hv * 64 + i * 16), Bsrc + i * 8);
        CP_COMMIT();
    }

    for (int c = 0; c < NC; c++) {
        const int s = c & 1;
        char* bufA = dbase + s * STAGE;

#pragma unroll
        for (int q = 0; q < 4; q++) {
            float4 v = pa[q];
            const u32 cbyte = (u32)(cf0 + q * 4) * 2;
            *(u64*)(bufA + swz((u32)r * 128 + cbyte)) =
                pack_f16x4(v.x, v.y, v.z, v.w);
        }
        if (c + 1 < NC) {
            const u32 bdst = base + ((c + 1) & 1) * STAGE + 16384;
            const __half* src = Bsrc + (c + 1) * KC;
#pragma unroll
            for (int i = 0; i < 4; i++)
                CP_ASYNC16(bdst + swz((u32)r * 128 + hv * 64 + i * 16), src + i * 8);
            CP_COMMIT();
            CP_WAIT1();
        } else {
            CP_WAIT0();
        }
        __syncthreads();

        if (c + 1 < NC) {
            const int kn = (c + 1) * KC;
#pragma unroll
            for (int q = 0; q < 4; q++)
                pa[q] = *(const float4*)(Arow + kn + cf0 + q * 4);
        }

        const u32 ab = base + s * STAGE;
        const u32 bb = ab + 16384;
#pragma unroll
        for (int ks = 0; ks < 2; ks++) {
            const u32 kA = (u32)(ks * 32 + cA);
            const u32 kB = (u32)(ks * 32 + cB);
            u32 ah[4][4], bf[2][4];
#pragma unroll
            for (int mt = 0; mt < 4; mt++)
                ldsm4(ah[mt], ab + swz((u32)(rA + mt * 16) * 128 + kA));
#pragma unroll
            for (int p = 0; p < 2; p++)
                ldsm4(bf[p], bb + swz((u32)(rB + p * 16) * 128 + kB));
#pragma unroll
            for (int mt = 0; mt < 4; mt++)
#pragma unroll
                for (int nt = 0; nt < 4; nt++)
                    mma_f16(acc[mt][nt], ah[mt], &bf[nt >> 1][(nt & 1) * 2]);
#pragma unroll
            for (int p = 0; p < 2; p++)
                ldsm4(bf[p], bb + swz((u32)(rB + p * 16) * 128 + 64 + kB));
#pragma unroll
            for (int mt = 0; mt < 4; mt++)
#pragma unroll
                for (int nt = 0; nt < 4; nt++)
                    mma_f16(acc[mt][nt], ah[mt], &bf[nt >> 1][(nt & 1) * 2]);
        }
        __syncthreads();
    }

    // fused epilogue: acc/256 -> smem -> column scan
    float* sc = (float*)dbase;
    const int er = lane >> 2;
    const int ec = (lane & 3) * 2;
#pragma unroll
    for (int mt = 0; mt < 4; mt++)
#pragma unroll
        for (int nt = 0; nt < 4; nt++) {
            const int m0 = wr * 64 + mt * 16 + er;
            const int n  = wc * 32 + nt * 8 + ec;
            *(float2*)(sc + m0 * 132 + n) =
                make_float2(acc[mt][nt][0] * W_DESCALE, acc[mt][nt][1] * W_DESCALE);
            *(float2*)(sc + (m0 + 8) * 132 + n) =
                make_float2(acc[mt][nt][2] * W_DESCALE, acc[mt][nt][3] * W_DESCALE);
        }
    __syncthreads();

    if (tid < 128) {
        const int n = tid;
        const float Aa = expf(log_A[n]);
        float h = 0.0f;
        float* dst = hsloc + row0 * N_DIM + n;
#pragma unroll 8
        for (int l = 0; l < 128; l++) {
            h = fmaf(Aa, h, sc[l * 132 + n]);
            dst[(size_t)l * N_DIM] = h;
        }
        carry[blockIdx.y * N_DIM + n] = h;
    }
}

// ───────── GEMM2 (fp16 2-chain): y = (hs @ Cw_scaled^T)/256 + x*Dp ─────────
// hs single fp16, C_w 2-term fp16 (x256). 4 virtual chunks of K'=64, 3 stages.
__global__ void __launch_bounds__(256, 2)
gemm2_hmma(const __half* __restrict__ hsf,
           const __half* __restrict__ Cwh, const __half* __restrict__ Cwl,
           float* __restrict__ C,
           const float* __restrict__ X, const float* __restrict__ Dp)
{
    constexpr int NVC = 4;
    constexpr int STAGE = 32768;

    extern __shared__ char dsm[];
    const u32 raw = smem_to_u32(dsm);
    const u32 base = (raw + 1023u) & ~1023u;

    const int tid  = threadIdx.x;
    const int lane = tid & 31;
    const int warp = tid >> 5;
    const int wr = warp & 1;
    const int wc = warp >> 1;
    const long row0 = (long)blockIdx.y * 128;
    const long col0 = (long)blockIdx.x * 128;

    const int r2 = tid >> 1;
    const int hv = tid & 1;

    const int g  = lane >> 3;
    const int ln = lane & 7;
    const int rA = wr * 64 + (g & 1) * 8 + ln;
    const int cA = (g >> 1) * 16;
    const int rB = wc * 32 + (g >> 1) * 8 + ln;
    const int cB = (g & 1) * 16;

    float acc[4][4][4];
#pragma unroll
    for (int i = 0; i < 4; i++)
#pragma unroll
        for (int j = 0; j < 4; j++)
#pragma unroll
            for (int q = 0; q < 4; q++) acc[i][j][q] = 0.0f;

    auto issue = [&](int vc) {
        const u32 sb = base + (vc % 3) * STAGE;
        const int t  = vc >> 1;          // 0: Ch, 1: Cl
        const int kk = (vc & 1) * 64;
        const __half* Bs = t ? Cwl : Cwh;
        const __half* asrc = hsf + (row0 + r2) * (long)N_DIM + kk + hv * 32;
        const __half* bsrc = Bs + (col0 + r2) * (long)N_DIM + kk + hv * 32;
#pragma unroll
        for (int i = 0; i < 4; i++)
            CP_ASYNC16(sb + swz((u32)r2 * 128 + hv * 64 + i * 16), asrc + i * 8);
#pragma unroll
        for (int i = 0; i < 4; i++)
            CP_ASYNC16(sb + 16384 + swz((u32)r2 * 128 + hv * 64 + i * 16), bsrc + i * 8);
        CP_COMMIT();
    };

    issue(0);
    issue(1);

    for (int vc = 0; vc < NVC; vc++) {
        if (vc + 1 < NVC) { CP_WAIT1(); } else { CP_WAIT0(); }
        __syncthreads();
        if (vc + 2 < NVC) issue(vc + 2);

        const u32 ab = base + (vc % 3) * STAGE;
        const u32 bb = ab + 16384;
#pragma unroll
        for (int ks = 0; ks < 4; ks++) {
            const u32 kA = (u32)(ks * 32 + cA);
            const u32 kB = (u32)(ks * 32 + cB);
            u32 ah[4][4], bf[2][4];
#pragma unroll
            for (int mt = 0; mt < 4; mt++)
                ldsm4(ah[mt], ab + swz((u32)(rA + mt * 16) * 128 + kA));
#pragma unroll
            for (int p = 0; p < 2; p++)
                ldsm4(bf[p], bb + swz((u32)(rB + p * 16) * 128 + kB));
#pragma unroll
            for (int mt = 0; mt < 4; mt++)
#pragma unroll
                for (int nt = 0; nt < 4; nt++)
                    mma_f16(acc[mt][nt], ah[mt], &bf[nt >> 1][(nt & 1) * 2]);
        }
        __syncthreads();
    }

    const int er = lane >> 2;
    const int ec = (lane & 3) * 2;
#pragma unroll
    for (int mt = 0; mt < 4; mt++)
#pragma unroll
        for (int nt = 0; nt < 4; nt++) {
            const long m = row0 + wr * 64 + mt * 16 + er;
            const long n = col0 + wc * 32 + nt * 8 + ec;
            float2 dv = *(const float2*)(Dp + n);
            float2 x0 = *(const float2*)(X + m * (long)D_DIM + n);
            float2 x1 = *(const float2*)(X + (m + 8) * (long)D_DIM + n);
            float2 o0, o1;
            o0.x = fmaf(x0.x, dv.x, acc[mt][nt][0] * W_DESCALE);
            o0.y = fmaf(x0.y, dv.y, acc[mt][nt][1] * W_DESCALE);
            o1.x = fmaf(x1.x, dv.x, acc[mt][nt][2] * W_DESCALE);
            o1.y = fmaf(x1.y, dv.y, acc[mt][nt][3] * W_DESCALE);
            *(float2*)(C + m * (long)D_DIM + n) = o0;
            *(float2*)(C + (m + 8) * (long)D_DIM + n) = o1;
        }
}

// ───────── fused weight presplit: both fp16 2-term, x256 ─────────
__global__ void split_both_kernel(const float* __restrict__ Bw, const float* __restrict__ Cw,
                                  __half* __restrict__ Bwh, __half* __restrict__ Bwl,
                                  __half* __restrict__ Cwh, __half* __restrict__ Cwl)
{
    const int nb = N_DIM * D_DIM;
    int i = blockIdx.x * blockDim.x + threadIdx.x;
    if (i < nb) {
        float v = Bw[i] * W_SCALE;
        __half h = __float2half_rn(v);
        Bwh[i] = h;
        Bwl[i] = __float2half_rn(v - __half2float(h));
    } else {
        int j = i - nb;
        if (j >= D_DIM * N_DIM) return;
        float v = Cw[j] * W_SCALE;
        __half h = __float2half_rn(v);
        Cwh[j] = h;
        Cwl[j] = __float2half_rn(v - __half2float(h));
    }
}

// ───────── carry scan + Apow + final_state (unchanged) ─────────
__global__ void __launch_bounds__(128)
carry_scan(const float* __restrict__ carry, float* __restrict__ prefix,
           const float* __restrict__ log_A, float* __restrict__ Apow,
           const float* __restrict__ hsloc, float* __restrict__ fs)
{
    int n = threadIdx.x;
    int b = blockIdx.x;
    float Aa = expf(log_A[n]);
    if (b == 0) {
        float pw = Aa;
#pragma unroll 8
        for (int i = 0; i < CHUNK; i++) {
            Apow[(size_t)i * N_DIM + n] = pw;   // A^(i+1)
            pw *= Aa;
        }
    }
    float Ac = expf((float)CHUNK * log_A[n]);
    float h = 0.0f;
#pragma unroll
    for (int c = 0; c < NCHUNK; c++) {
        prefix[(b * NCHUNK + c) * N_DIM + n] = h;   // exclusive
        h = fmaf(Ac, h, carry[(b * NCHUNK + c) * N_DIM + n]);
    }
    float s = 0.0f;
#pragma unroll
    for (int bb = 0; bb < B_DIM; bb++) {
        float hL1 = hsloc[((size_t)bb * L_DIM + (L_DIM - 1)) * N_DIM + n];
        float hL2 = hsloc[((size_t)bb * L_DIM + (L_DIM - 2)) * N_DIM + n];
        s += hL1 - Aa * hL2;
    }
    fs[b * N_DIM + n] = s * (1.0f / B_DIM);
}

// ───────── fix + convert: hs = hs_local + Apow*prefix -> single fp16 ─────────
__global__ void __launch_bounds__(256)
fix_split(const float* __restrict__ hsloc, const float* __restrict__ prefix,
          const float* __restrict__ Apow, __half* __restrict__ hsf)
{
    size_t i = ((size_t)blockIdx.x * 256 + threadIdx.x) * 4;
    const int m  = (int)(i >> 7);
    const int n0 = (int)(i & 127);
    float4 v  = *(const float4*)(hsloc + i);
    float4 ap = *(const float4*)(Apow + ((size_t)(m & 127) << 7) + n0);
    float4 pf = *(const float4*)(prefix + ((size_t)(m >> 7) << 7) + n0);
    float hx = fmaf(ap.x, pf.x, v.x);
    float hy = fmaf(ap.y, pf.y, v.y);
    float hz = fmaf(ap.z, pf.z, v.z);
    float hw = fmaf(ap.w, pf.w, v.w);
    *(u64*)(hsf + i) = pack_f16x4(hx, hy, hz, hw);
}

// ─────────────────────────────── launch ───────────────────────────────
extern "C" void kernel_launch(void* const* d_in, const int* in_sizes, int n_in,
                              void* d_out, int out_size)
{
    const float* x       = (const float*)d_in[0];
    const float* B_w     = (const float*)d_in[1];
    const float* C_w     = (const float*)d_in[2];
    const float* log_A   = (const float*)d_in[3];
    const float* D_param = (const float*)d_in[4];

    float* y  = (float*)d_out;
    float* fs = y + ((size_t)out_size - (size_t)B_DIM * N_DIM);

    float *hsloc, *carry, *prefix, *Apow;
    __half *hsf, *Bwh, *Bwl, *Cwh, *Cwl;
    cudaGetSymbolAddress((void**)&hsloc, g_hsloc);
    cudaGetSymbolAddress((void**)&carry, g_carry);
    cudaGetSymbolAddress((void**)&prefix, g_prefix);
    cudaGetSymbolAddress((void**)&Apow, g_Apow);
    cudaGetSymbolAddress((void**)&hsf, g_hsf);
    cudaGetSymbolAddress((void**)&Bwh, g_Bwh);
    cudaGetSymbolAddress((void**)&Bwl, g_Bwl);
    cudaGetSymbolAddress((void**)&Cwh, g_Cwh);
    cudaGetSymbolAddress((void**)&Cwl, g_Cwl);

    const int SMEM1 = 128 * 132 * 4 + 1024;   // 68608
    const int SMEM2 = 3 * 32768 + 1024;       // 99328
    cudaFuncSetAttribute(gemm1_hmma, cudaFuncAttributeMaxDynamicSharedMemorySize, SMEM1);
    cudaFuncSetAttribute(gemm2_hmma, cudaFuncAttributeMaxDynamicSharedMemorySize, SMEM2);

    split_both_kernel<<<(2 * N_DIM * D_DIM + 255) / 256, 256>>>(B_w, C_w, Bwh, Bwl, Cwh, Cwl);

    // GEMM1 (fp16 2-chain) + fused local scan
    {
        dim3 grid(1, M_TOTAL / 128);
        gemm1_hmma<<<grid, 256, SMEM1>>>(x, Bwh, Bwl, hsloc, carry, log_A);
    }

    // carry prefix (+Apow, +final_state)
    carry_scan<<<B_DIM, 128>>>(carry, prefix, log_A, Apow, hsloc, fs);

    // elementwise fix + fp16 convert
    fix_split<<<(int)(((size_t)M_TOTAL * N_DIM / 4) / 256), 256>>>(hsloc, prefix, Apow, hsf);

    // GEMM2 (fp16 2-chain): y = hs @ C_w^T + x * D_param
    {
        dim3 grid(D_DIM / 128, M_TOTAL / 128);
        gemm2_hmma<<<grid, 256, SMEM2>>>(hsf, Cwh, Cwl, y, x, D_param);
    }
}

// round 17
// speedup vs baseline: 1.9517x; 1.3759x over previous
#include <cuda_runtime.h>
#include <cuda_fp16.h>
#include <cstdint>

#define B_DIM 8
#define L_DIM 4096
#define D_DIM 1024
#define N_DIM 128
#define M_TOTAL (B_DIM * L_DIM)   // 32768
#define CHUNK 128
#define NCHUNK (L_DIM / CHUNK)    // 32
#define TOT_CHUNKS (B_DIM * NCHUNK) // 256

// Scratch (no cudaMalloc allowed)
__device__ float g_hsloc[(size_t)M_TOTAL * N_DIM];    // local scans, fp32
__device__ float g_carry[TOT_CHUNKS * N_DIM];
__device__ float g_prefix[TOT_CHUNKS * N_DIM];
__device__ float g_Apow[CHUNK * N_DIM];               // A^(i+1)
__device__ __half g_hsf[(size_t)M_TOTAL * N_DIM];     // fixed hs, fp16
__device__ __half g_Bwh[N_DIM * D_DIM];               // fp16 single
__device__ __half g_Cwh[D_DIM * N_DIM];               // fp16 single

typedef unsigned long long u64;
typedef uint32_t u32;

__device__ __forceinline__ u32 smem_to_u32(const void* p) {
    u32 a;
    asm("{ .reg .u64 t; cvta.to.shared.u64 t, %1; cvt.u32.u64 %0, t; }"
        : "=r"(a) : "l"(p));
    return a;
}
__device__ __forceinline__ u32 swz(u32 o) { return o ^ ((o >> 3) & 0x70); }

__device__ __forceinline__ void ldsm4(u32* r, u32 addr) {
    asm volatile("ldmatrix.sync.aligned.m8n8.x4.shared.b16 {%0,%1,%2,%3}, [%4];"
                 : "=r"(r[0]), "=r"(r[1]), "=r"(r[2]), "=r"(r[3]) : "r"(addr));
}
__device__ __forceinline__ void mma_f16(float* c, const u32* a, const u32* b) {
    asm volatile("mma.sync.aligned.m16n8k16.row.col.f32.f16.f16.f32 "
                 "{%0,%1,%2,%3}, {%4,%5,%6,%7}, {%8,%9}, {%0,%1,%2,%3};"
                 : "+f"(c[0]), "+f"(c[1]), "+f"(c[2]), "+f"(c[3])
                 : "r"(a[0]), "r"(a[1]), "r"(a[2]), "r"(a[3]),
                   "r"(b[0]), "r"(b[1]));
}
__device__ __forceinline__ u64 pack_f16x4(float a, float b, float c, float d) {
    __half2 p0 = __floats2half2_rn(a, b);
    __half2 p1 = __floats2half2_rn(c, d);
    u32 lo = *(u32*)&p0, hi = *(u32*)&p1;
    return ((u64)hi << 32) | lo;
}
#define CP_ASYNC16(dst, src) \
    asm volatile("cp.async.cg.shared.global [%0], [%1], 16;" :: "r"(dst), "l"(src))
#define CP_COMMIT() asm volatile("cp.async.commit_group;")
#define CP_WAIT0() asm volatile("cp.async.wait_group 0;")
#define CP_WAIT1() asm volatile("cp.async.wait_group 1;")

// ───────── GEMM1 (fp16 1-chain): hs_local/carry = scan_local(x @ B_w^T) ─────
// A (x) → single fp16 in-kernel; B → single fp16 presplit. One mma chain.
__global__ void __launch_bounds__(256)
gemm1_hmma(const float* __restrict__ A,
           const __half* __restrict__ Bwh,
           float* __restrict__ hsloc, float* __restrict__ carry,
           const float* __restrict__ log_A)
{
    constexpr int KTOT = D_DIM;
    constexpr int KC = 32;
    constexpr int NC = KTOT / KC;      // 32
    constexpr int STAGE = 32768;

    extern __shared__ char dsm[];
    const u32 raw = smem_to_u32(dsm);
    const u32 base = (raw + 1023u) & ~1023u;
    char* dbase = dsm + (base - raw);

    const int tid  = threadIdx.x;
    const int lane = tid & 31;
    const int warp = tid >> 5;
    const int wr = warp & 1;
    const int wc = warp >> 1;
    const long row0 = (long)blockIdx.y * 128;

    const int r   = tid >> 1;
    const int hv  = tid & 1;
    const int cf0 = hv * 16;
    const float* Arow = A + (row0 + r) * (long)KTOT;
    const __half* Bsrc = Bwh + (size_t)r * KTOT;

    const int g  = lane >> 3;
    const int ln = lane & 7;
    const int rA = wr * 64 + (g & 1) * 8 + ln;
    const int cA = (g >> 1) * 16;
    const int rB = wc * 32 + (g >> 1) * 8 + ln;
    const int cB = (g & 1) * 16;

    float acc[4][4][4];
#pragma unroll
    for (int i = 0; i < 4; i++)
#pragma unroll
        for (int j = 0; j < 4; j++)
#pragma unroll
            for (int q = 0; q < 4; q++) acc[i][j][q] = 0.0f;

    float4 pa[4];
#pragma unroll
    for (int q = 0; q < 4; q++) pa[q] = *(const float4*)(Arow + cf0 + q * 4);
    // B chunk 0: only hv==0 threads load (64B/row = 32 fp16)
    if (hv == 0) {
        const u32 bdst = base + 16384;
#pragma unroll
        for (int i = 0; i < 4; i++)
            CP_ASYNC16(bdst + swz((u32)r * 128 + i * 16), Bsrc + i * 8);
    }
    CP_COMMIT();

    for (int c = 0; c < NC; c++) {
        const int s = c & 1;
        char* bufA = dbase + s * STAGE;

        // convert A chunk c: single fp16 (16 fp32 per thread)
#pragma unroll
        for (int q = 0; q < 4; q++) {
            float4 v = pa[q];
            const u32 cbyte = (u32)(cf0 + q * 4) * 2;
            *(u64*)(bufA + swz((u32)r * 128 + cbyte)) =
                pack_f16x4(v.x, v.y, v.z, v.w);
        }
        if (c + 1 < NC) {
            if (hv == 0) {
                const u32 bdst = base + ((c + 1) & 1) * STAGE + 16384;
                const __half* src = Bsrc + (c + 1) * KC;
#pragma unroll
                for (int i = 0; i < 4; i++)
                    CP_ASYNC16(bdst + swz((u32)r * 128 + i * 16), src + i * 8);
            }
            CP_COMMIT();
            CP_WAIT1();
        } else {
            CP_WAIT0();
        }
        __syncthreads();

        if (c + 1 < NC) {
            const int kn = (c + 1) * KC;
#pragma unroll
            for (int q = 0; q < 4; q++)
                pa[q] = *(const float4*)(Arow + kn + cf0 + q * 4);
        }

        const u32 ab = base + s * STAGE;
        const u32 bb = ab + 16384;
#pragma unroll
        for (int ks = 0; ks < 2; ks++) {
            const u32 kA = (u32)(ks * 32 + cA);
            const u32 kB = (u32)(ks * 32 + cB);
            u32 ah[4][4], bf[2][4];
#pragma unroll
            for (int mt = 0; mt < 4; mt++)
                ldsm4(ah[mt], ab + swz((u32)(rA + mt * 16) * 128 + kA));
#pragma unroll
            for (int p = 0; p < 2; p++)
                ldsm4(bf[p], bb + swz((u32)(rB + p * 16) * 128 + kB));
#pragma unroll
            for (int mt = 0; mt < 4; mt++)
#pragma unroll
                for (int nt = 0; nt < 4; nt++)
                    mma_f16(acc[mt][nt], ah[mt], &bf[nt >> 1][(nt & 1) * 2]);
        }
        __syncthreads();
    }

    // fused epilogue: acc -> smem -> column scan
    float* sc = (float*)dbase;
    const int er = lane >> 2;
    const int ec = (lane & 3) * 2;
#pragma unroll
    for (int mt = 0; mt < 4; mt++)
#pragma unroll
        for (int nt = 0; nt < 4; nt++) {
            const int m0 = wr * 64 + mt * 16 + er;
            const int n  = wc * 32 + nt * 8 + ec;
            *(float2*)(sc + m0 * 132 + n)       = make_float2(acc[mt][nt][0], acc[mt][nt][1]);
            *(float2*)(sc + (m0 + 8) * 132 + n) = make_float2(acc[mt][nt][2], acc[mt][nt][3]);
        }
    __syncthreads();

    if (tid < 128) {
        const int n = tid;
        const float Aa = expf(log_A[n]);
        float h = 0.0f;
        float* dst = hsloc + row0 * N_DIM + n;
#pragma unroll 8
        for (int l = 0; l < 128; l++) {
            h = fmaf(Aa, h, sc[l * 132 + n]);
            dst[(size_t)l * N_DIM] = h;
        }
        carry[blockIdx.y * N_DIM + n] = h;
    }
}

// ───────── GEMM2 (fp16 1-chain): y = hs @ C_w^T + x*Dp ─────────
// hs single fp16, C_w single fp16. 2 chunks of K'=64, double-buffered.
__global__ void __launch_bounds__(256, 2)
gemm2_hmma(const __half* __restrict__ hsf,
           const __half* __restrict__ Cwh,
           float* __restrict__ C,
           const float* __restrict__ X, const float* __restrict__ Dp)
{
    constexpr int NVC = 2;
    constexpr int STAGE = 32768;

    extern __shared__ char dsm[];
    const u32 raw = smem_to_u32(dsm);
    const u32 base = (raw + 1023u) & ~1023u;

    const int tid  = threadIdx.x;
    const int lane = tid & 31;
    const int warp = tid >> 5;
    const int wr = warp & 1;
    const int wc = warp >> 1;
    const long row0 = (long)blockIdx.y * 128;
    const long col0 = (long)blockIdx.x * 128;

    const int r2 = tid >> 1;
    const int hv = tid & 1;

    const int g  = lane >> 3;
    const int ln = lane & 7;
    const int rA = wr * 64 + (g & 1) * 8 + ln;
    const int cA = (g >> 1) * 16;
    const int rB = wc * 32 + (g >> 1) * 8 + ln;
    const int cB = (g & 1) * 16;

    float acc[4][4][4];
#pragma unroll
    for (int i = 0; i < 4; i++)
#pragma unroll
        for (int j = 0; j < 4; j++)
#pragma unroll
            for (int q = 0; q < 4; q++) acc[i][j][q] = 0.0f;

    auto issue = [&](int vc) {
        const u32 sb = base + (vc & 1) * STAGE;
        const int kk = vc * 64;
        const __half* asrc = hsf + (row0 + r2) * (long)N_DIM + kk + hv * 32;
        const __half* bsrc = Cwh + (col0 + r2) * (long)N_DIM + kk + hv * 32;
#pragma unroll
        for (int i = 0; i < 4; i++)
            CP_ASYNC16(sb + swz((u32)r2 * 128 + hv * 64 + i * 16), asrc + i * 8);
#pragma unroll
        for (int i = 0; i < 4; i++)
            CP_ASYNC16(sb + 16384 + swz((u32)r2 * 128 + hv * 64 + i * 16), bsrc + i * 8);
        CP_COMMIT();
    };

    issue(0);
    issue(1);

    for (int vc = 0; vc < NVC; vc++) {
        if (vc + 1 < NVC) { CP_WAIT1(); } else { CP_WAIT0(); }
        __syncthreads();

        const u32 ab = base + (vc & 1) * STAGE;
        const u32 bb = ab + 16384;
#pragma unroll
        for (int ks = 0; ks < 4; ks++) {
            const u32 kA = (u32)(ks * 32 + cA);
            const u32 kB = (u32)(ks * 32 + cB);
            u32 ah[4][4], bf[2][4];
#pragma unroll
            for (int mt = 0; mt < 4; mt++)
                ldsm4(ah[mt], ab + swz((u32)(rA + mt * 16) * 128 + kA));
#pragma unroll
            for (int p = 0; p < 2; p++)
                ldsm4(bf[p], bb + swz((u32)(rB + p * 16) * 128 + kB));
#pragma unroll
            for (int mt = 0; mt < 4; mt++)
#pragma unroll
                for (int nt = 0; nt < 4; nt++)
                    mma_f16(acc[mt][nt], ah[mt], &bf[nt >> 1][(nt & 1) * 2]);
        }
        __syncthreads();
    }

    const int er = lane >> 2;
    const int ec = (lane & 3) * 2;
#pragma unroll
    for (int mt = 0; mt < 4; mt++)
#pragma unroll
        for (int nt = 0; nt < 4; nt++) {
            const long m = row0 + wr * 64 + mt * 16 + er;
            const long n = col0 + wc * 32 + nt * 8 + ec;
            float2 dv = *(const float2*)(Dp + n);
            float2 x0 = *(const float2*)(X + m * (long)D_DIM + n);
            float2 x1 = *(const float2*)(X + (m + 8) * (long)D_DIM + n);
            float2 o0, o1;
            o0.x = fmaf(x0.x, dv.x, acc[mt][nt][0]);
            o0.y = fmaf(x0.y, dv.y, acc[mt][nt][1]);
            o1.x = fmaf(x1.x, dv.x, acc[mt][nt][2]);
            o1.y = fmaf(x1.y, dv.y, acc[mt][nt][3]);
            *(float2*)(C + m * (long)D_DIM + n) = o0;
            *(float2*)(C + (m + 8) * (long)D_DIM + n) = o1;
        }
}

// ───────── fused weight convert: both single fp16 ─────────
__global__ void split_both_kernel(const float* __restrict__ Bw, const float* __restrict__ Cw,
                                  __half* __restrict__ Bwh, __half* __restrict__ Cwh)
{
    const int nb = N_DIM * D_DIM;
    int i = blockIdx.x * blockDim.x + threadIdx.x;
    if (i < nb) {
        Bwh[i] = __float2half_rn(Bw[i]);
    } else {
        int j = i - nb;
        if (j >= D_DIM * N_DIM) return;
        Cwh[j] = __float2half_rn(Cw[j]);
    }
}

// ───────── carry scan + Apow + final_state (unchanged) ─────────
__global__ void __launch_bounds__(128)
carry_scan(const float* __restrict__ carry, float* __restrict__ prefix,
           const float* __restrict__ log_A, float* __restrict__ Apow,
           const float* __restrict__ hsloc, float* __restrict__ fs)
{
    int n = threadIdx.x;
    int b = blockIdx.x;
    float Aa = expf(log_A[n]);
    if (b == 0) {
        float pw = Aa;
#pragma unroll 8
        for (int i = 0; i < CHUNK; i++) {
            Apow[(size_t)i * N_DIM + n] = pw;   // A^(i+1)
            pw *= Aa;
        }
    }
    float Ac = expf((float)CHUNK * log_A[n]);
    float h = 0.0f;
#pragma unroll
    for (int c = 0; c < NCHUNK; c++) {
        prefix[(b * NCHUNK + c) * N_DIM + n] = h;   // exclusive
        h = fmaf(Ac, h, carry[(b * NCHUNK + c) * N_DIM + n]);
    }
    float s = 0.0f;
#pragma unroll
    for (int bb = 0; bb < B_DIM; bb++) {
        float hL1 = hsloc[((size_t)bb * L_DIM + (L_DIM - 1)) * N_DIM + n];
        float hL2 = hsloc[((size_t)bb * L_DIM + (L_DIM - 2)) * N_DIM + n];
        s += hL1 - Aa * hL2;
    }
    fs[b * N_DIM + n] = s * (1.0f / B_DIM);
}

// ───────── fix + convert: hs = hs_local + Apow*prefix -> single fp16 ─────────
__global__ void __launch_bounds__(256)
fix_split(const float* __restrict__ hsloc, const float* __restrict__ prefix,
          const float* __restrict__ Apow, __half* __restrict__ hsf)
{
    size_t i = ((size_t)blockIdx.x * 256 + threadIdx.x) * 4;
    const int m  = (int)(i >> 7);
    const int n0 = (int)(i & 127);
    float4 v  = *(const float4*)(hsloc + i);
    float4 ap = *(const float4*)(Apow + ((size_t)(m & 127) << 7) + n0);
    float4 pf = *(const float4*)(prefix + ((size_t)(m >> 7) << 7) + n0);
    float hx = fmaf(ap.x, pf.x, v.x);
    float hy = fmaf(ap.y, pf.y, v.y);
    float hz = fmaf(ap.z, pf.z, v.z);
    float hw = fmaf(ap.w, pf.w, v.w);
    *(u64*)(hsf + i) = pack_f16x4(hx, hy, hz, hw);
}

// ─────────────────────────────── launch ───────────────────────────────
extern "C" void kernel_launch(void* const* d_in, const int* in_sizes, int n_in,
                              void* d_out, int out_size)
{
    const float* x       = (const float*)d_in[0];
    const float* B_w     = (const float*)d_in[1];
    const float* C_w     = (const float*)d_in[2];
    const float* log_A   = (const float*)d_in[3];
    const float* D_param = (const float*)d_in[4];

    float* y  = (float*)d_out;
    float* fs = y + ((size_t)out_size - (size_t)B_DIM * N_DIM);

    float *hsloc, *carry, *prefix, *Apow;
    __half *hsf, *Bwh, *Cwh;
    cudaGetSymbolAddress((void**)&hsloc, g_hsloc);
    cudaGetSymbolAddress((void**)&carry, g_carry);
    cudaGetSymbolAddress((void**)&prefix, g_prefix);
    cudaGetSymbolAddress((void**)&Apow, g_Apow);
    cudaGetSymbolAddress((void**)&hsf, g_hsf);
    cudaGetSymbolAddress((void**)&Bwh, g_Bwh);
    cudaGetSymbolAddress((void**)&Cwh, g_Cwh);

    const int SMEM1 = 128 * 132 * 4 + 1024;   // 68608
    const int SMEM2 = 2 * 32768 + 1024;       // 66560
    cudaFuncSetAttribute(gemm1_hmma, cudaFuncAttributeMaxDynamicSharedMemorySize, SMEM1);
    cudaFuncSetAttribute(gemm2_hmma, cudaFuncAttributeMaxDynamicSharedMemorySize, SMEM2);

    split_both_kernel<<<(2 * N_DIM * D_DIM + 255) / 256, 256>>>(B_w, C_w, Bwh, Cwh);

    // GEMM1 (fp16 1-chain) + fused local scan
    {
        dim3 grid(1, M_TOTAL / 128);
        gemm1_hmma<<<grid, 256, SMEM1>>>(x, Bwh, hsloc, carry, log_A);
    }

    // carry prefix (+Apow, +final_state)
    carry_scan<<<B_DIM, 128>>>(carry, prefix, log_A, Apow, hsloc, fs);

    // elementwise fix + fp16 convert
    fix_split<<<(int)(((size_t)M_TOTAL * N_DIM / 4) / 256), 256>>>(hsloc, prefix, Apow, hsf);

    // GEMM2 (fp16 1-chain): y = hs @ C_w^T + x * D_param
    {
        dim3 grid(D_DIM / 128, M_TOTAL / 128);
        gemm2_hmma<<<grid, 256, SMEM2>>>(hsf, Cwh, y, x, D_param);
    }
}